// round 2
// baseline (speedup 1.0000x reference)
#include <cuda_runtime.h>
#include <mma.h>
#include <math.h>

using namespace nvcuda;

// Problem constants
#define BB   4
#define NN   2048
#define DIN  1024
#define DOUTC 1024
#define HH   16
#define HD   64

// Scratch (allocation-free: __device__ globals)
__device__ float g_q[BB*HH*NN*HD];    // [b,h,n,d]
__device__ float g_k[BB*HH*NN*HD];
__device__ float g_v[BB*HH*NN*HD];
__device__ float g_ctx[BB*NN*DOUTC];  // [b,n, h*64+d]

// ---------------------------------------------------------------------------
// QKV projection: y = x @ W, written head-major. Block tile 128x64, BK=32.
// 8 warps (4x2), each warp 32x32 via 2x2 wmma m16n16k8 tf32 fragments.
// blockIdx.z selects Q/K/V. BN=64 == one head => head-major store is row-major ld=64.
// ---------------------------------------------------------------------------
__global__ __launch_bounds__(256) void qkv_gemm(
    const float* __restrict__ x,
    const float* __restrict__ Wq,
    const float* __restrict__ Wk,
    const float* __restrict__ Wv)
{
    __shared__ float As[128][40];   // [m][k], padded
    __shared__ float Bs[32][72];    // [k][n], padded

    const int tid = threadIdx.x;
    const int wid = tid >> 5;
    const int warp_m = wid >> 1;    // 0..3
    const int warp_n = wid & 1;     // 0..1
    const int m0 = blockIdx.x * 128;
    const int h  = blockIdx.y;      // head index; n0 = h*64
    const int z  = blockIdx.z;

    const float* W   = (z == 0) ? Wq : ((z == 1) ? Wk : Wv);
    float* outb      = (z == 0) ? g_q : ((z == 1) ? g_k : g_v);

    wmma::fragment<wmma::accumulator, 16, 16, 8, float> acc[2][2];
    #pragma unroll
    for (int mi = 0; mi < 2; mi++)
        #pragma unroll
        for (int ni = 0; ni < 2; ni++)
            wmma::fill_fragment(acc[mi][ni], 0.0f);

    for (int k0 = 0; k0 < DIN; k0 += 32) {
        // Load A tile: 128x32 floats = 1024 float4, 4 per thread
        #pragma unroll
        for (int r = 0; r < 4; r++) {
            int f4 = tid + 256 * r;
            int m  = f4 >> 3;
            int kk = (f4 & 7) << 2;
            float4 v = *(const float4*)(x + (size_t)(m0 + m) * DIN + k0 + kk);
            *(float4*)(&As[m][kk]) = v;
        }
        // Load B tile: 32x64 floats = 512 float4, 2 per thread
        #pragma unroll
        for (int r = 0; r < 2; r++) {
            int f4 = tid + 256 * r;
            int kk = f4 >> 4;
            int n  = (f4 & 15) << 2;
            float4 v = *(const float4*)(W + (size_t)(k0 + kk) * DOUTC + h * 64 + n);
            *(float4*)(&Bs[kk][n]) = v;
        }
        __syncthreads();

        #pragma unroll
        for (int ks = 0; ks < 4; ks++) {
            wmma::fragment<wmma::matrix_a, 16, 16, 8, wmma::precision::tf32, wmma::row_major> af[2];
            wmma::fragment<wmma::matrix_b, 16, 16, 8, wmma::precision::tf32, wmma::row_major> bf[2];
            #pragma unroll
            for (int mi = 0; mi < 2; mi++) {
                wmma::load_matrix_sync(af[mi], &As[warp_m * 32 + mi * 16][ks * 8], 40);
                #pragma unroll
                for (int t = 0; t < af[mi].num_elements; t++)
                    af[mi].x[t] = wmma::__float_to_tf32(af[mi].x[t]);
            }
            #pragma unroll
            for (int ni = 0; ni < 2; ni++) {
                wmma::load_matrix_sync(bf[ni], &Bs[ks * 8][warp_n * 32 + ni * 16], 72);
                #pragma unroll
                for (int t = 0; t < bf[ni].num_elements; t++)
                    bf[ni].x[t] = wmma::__float_to_tf32(bf[ni].x[t]);
            }
            #pragma unroll
            for (int mi = 0; mi < 2; mi++)
                #pragma unroll
                for (int ni = 0; ni < 2; ni++)
                    wmma::mma_sync(acc[mi][ni], af[mi], bf[ni], acc[mi][ni]);
        }
        __syncthreads();
    }

    // Store head-major: out[((b*H+h)*N + n)*64 + d]
    const int b  = m0 / NN;
    const int nb = m0 % NN;
    float* base = outb + ((size_t)(b * HH + h) * NN + nb) * HD;
    #pragma unroll
    for (int mi = 0; mi < 2; mi++)
        #pragma unroll
        for (int ni = 0; ni < 2; ni++)
            wmma::store_matrix_sync(
                base + (warp_m * 32 + mi * 16) * HD + warp_n * 32 + ni * 16,
                acc[mi][ni], HD, wmma::mem_row_major);
}

// ---------------------------------------------------------------------------
// Flash-style attention with online softmax. 64x64 tiles, causal kt<=qt loop.
// Grid: (N/64, B*H). 256 threads, 8 warps in 4x2 over the 64x64 tile.
// Dynamic smem layout (floats, ld=72 padding):
//   sQ[64*72] sK[64*72] sV[64*72] sS[64*72] sO[64*72] sMx[64] sL[64] mask[64]
// ---------------------------------------------------------------------------
#define TLD 72
#define ATTN_SMEM_BYTES ((5*64*TLD + 64 + 64 + 64) * 4)

__global__ __launch_bounds__(256) void attn_kernel(const int* __restrict__ amask)
{
    extern __shared__ float sm[];
    float* sQ  = sm;
    float* sK  = sQ + 64 * TLD;
    float* sV  = sK + 64 * TLD;
    float* sS  = sV + 64 * TLD;
    float* sO  = sS + 64 * TLD;
    float* sMx = sO + 64 * TLD;
    float* sL  = sMx + 64;
    int*   sMask = (int*)(sL + 64);

    const int tid = threadIdx.x;
    const int wid = tid >> 5;
    const int warp_i = wid >> 1;    // 0..3 : 16-row groups
    const int warp_j = wid & 1;     // 0..1 : 32-col groups
    const int qt = blockIdx.x;
    const int bh = blockIdx.y;
    const int b  = bh >> 4;
    const int q0 = qt * 64;

    // Load Q tile
    const float* qbase = g_q + ((size_t)bh * NN + q0) * HD;
    #pragma unroll
    for (int r = 0; r < 4; r++) {
        int f4 = tid + 256 * r;
        int i  = f4 >> 4;
        int d  = (f4 & 15) << 2;
        *(float4*)(&sQ[i * TLD + d]) = *(const float4*)(qbase + (size_t)i * HD + d);
    }
    for (int idx = tid; idx < 64 * TLD; idx += 256) sO[idx] = 0.0f;
    if (tid < 64) { sMx[tid] = -INFINITY; sL[tid] = 0.0f; }
    __syncthreads();

    for (int kt = 0; kt <= qt; kt++) {
        const int k0 = kt * 64;
        const float* kbase = g_k + ((size_t)bh * NN + k0) * HD;
        const float* vbase = g_v + ((size_t)bh * NN + k0) * HD;
        #pragma unroll
        for (int r = 0; r < 4; r++) {
            int f4 = tid + 256 * r;
            int i  = f4 >> 4;
            int d  = (f4 & 15) << 2;
            *(float4*)(&sK[i * TLD + d]) = *(const float4*)(kbase + (size_t)i * HD + d);
            *(float4*)(&sV[i * TLD + d]) = *(const float4*)(vbase + (size_t)i * HD + d);
        }
        if (tid < 64) sMask[tid] = amask[b * NN + k0 + tid];
        __syncthreads();

        // S = (Q K^T) * 0.125
        {
            wmma::fragment<wmma::accumulator, 16, 16, 8, float> sacc[2];
            wmma::fill_fragment(sacc[0], 0.0f);
            wmma::fill_fragment(sacc[1], 0.0f);
            #pragma unroll
            for (int ks = 0; ks < 8; ks++) {
                wmma::fragment<wmma::matrix_a, 16, 16, 8, wmma::precision::tf32, wmma::row_major> af;
                wmma::load_matrix_sync(af, &sQ[(warp_i * 16) * TLD + ks * 8], TLD);
                #pragma unroll
                for (int t = 0; t < af.num_elements; t++)
                    af.x[t] = wmma::__float_to_tf32(af.x[t]);
                #pragma unroll
                for (int ni = 0; ni < 2; ni++) {
                    wmma::fragment<wmma::matrix_b, 16, 16, 8, wmma::precision::tf32, wmma::col_major> bf;
                    wmma::load_matrix_sync(bf, &sK[(warp_j * 32 + ni * 16) * TLD + ks * 8], TLD);
                    #pragma unroll
                    for (int t = 0; t < bf.num_elements; t++)
                        bf.x[t] = wmma::__float_to_tf32(bf.x[t]);
                    wmma::mma_sync(sacc[ni], af, bf, sacc[ni]);
                }
            }
            #pragma unroll
            for (int ni = 0; ni < 2; ni++) {
                #pragma unroll
                for (int t = 0; t < sacc[ni].num_elements; t++)
                    sacc[ni].x[t] *= 0.125f;   // 1/sqrt(64)
                wmma::store_matrix_sync(&sS[(warp_i * 16) * TLD + warp_j * 32 + ni * 16],
                                        sacc[ni], TLD, wmma::mem_row_major);
            }
        }
        __syncthreads();

        // Mask: causal (global key > global query) and padding
        #pragma unroll
        for (int e = 0; e < 16; e++) {
            int flat = tid * 16 + e;
            int i = flat >> 6;
            int j = flat & 63;
            bool bad = ((k0 + j) > (q0 + i)) || (sMask[j] == 0);
            if (bad) sS[i * TLD + j] = -1e30f;
        }
        __syncthreads();

        // Online softmax: 4 threads per row
        {
            const int r   = tid >> 2;
            const int sub = tid & 3;
            float mx = -INFINITY;
            for (int c = sub; c < 64; c += 4) mx = fmaxf(mx, sS[r * TLD + c]);
            mx = fmaxf(mx, __shfl_xor_sync(0xffffffffu, mx, 1));
            mx = fmaxf(mx, __shfl_xor_sync(0xffffffffu, mx, 2));
            const float mold = sMx[r];
            const float mnew = fmaxf(mold, mx);
            const float alpha = __expf(mold - mnew);
            float sum = 0.0f;
            for (int c = sub; c < 64; c += 4) {
                float p = __expf(sS[r * TLD + c] - mnew);
                sS[r * TLD + c] = p;
                sum += p;
            }
            sum += __shfl_xor_sync(0xffffffffu, sum, 1);
            sum += __shfl_xor_sync(0xffffffffu, sum, 2);
            if (sub == 0) { sMx[r] = mnew; sL[r] = sL[r] * alpha + sum; }
            // rescale O row by alpha (16 contiguous cols per thread)
            float* orow = &sO[r * TLD + sub * 16];
            #pragma unroll
            for (int c = 0; c < 16; c++) orow[c] *= alpha;
        }
        __syncthreads();

        // O += P @ V
        {
            wmma::fragment<wmma::accumulator, 16, 16, 8, float> oacc[2];
            #pragma unroll
            for (int ni = 0; ni < 2; ni++)
                wmma::load_matrix_sync(oacc[ni],
                    &sO[(warp_i * 16) * TLD + warp_j * 32 + ni * 16], TLD, wmma::mem_row_major);
            #pragma unroll
            for (int ks = 0; ks < 8; ks++) {
                wmma::fragment<wmma::matrix_a, 16, 16, 8, wmma::precision::tf32, wmma::row_major> pf;
                wmma::load_matrix_sync(pf, &sS[(warp_i * 16) * TLD + ks * 8], TLD);
                #pragma unroll
                for (int t = 0; t < pf.num_elements; t++)
                    pf.x[t] = wmma::__float_to_tf32(pf.x[t]);
                #pragma unroll
                for (int ni = 0; ni < 2; ni++) {
                    wmma::fragment<wmma::matrix_b, 16, 16, 8, wmma::precision::tf32, wmma::row_major> vf;
                    wmma::load_matrix_sync(vf, &sV[(ks * 8) * TLD + warp_j * 32 + ni * 16], TLD);
                    #pragma unroll
                    for (int t = 0; t < vf.num_elements; t++)
                        vf.x[t] = wmma::__float_to_tf32(vf.x[t]);
                    wmma::mma_sync(oacc[ni], pf, vf, oacc[ni]);
                }
            }
            #pragma unroll
            for (int ni = 0; ni < 2; ni++)
                wmma::store_matrix_sync(&sO[(warp_i * 16) * TLD + warp_j * 32 + ni * 16],
                                        oacc[ni], TLD, wmma::mem_row_major);
        }
        __syncthreads();
    }

    // Normalize and write ctx[b, n, h*64+d]
    const int h = bh & 15;
    float* ctxbase = g_ctx + ((size_t)(b * NN) + q0) * DOUTC + h * HD;
    #pragma unroll
    for (int e = 0; e < 16; e++) {
        int flat = tid * 16 + e;
        int i = flat >> 6;
        int d = flat & 63;
        ctxbase[(size_t)i * DOUTC + d] = sO[i * TLD + d] / sL[i];
    }
}

// ---------------------------------------------------------------------------
// Output projection: out = ctx @ Wo (bias added in a follow-up kernel)
// ---------------------------------------------------------------------------
__global__ __launch_bounds__(256) void out_gemm(
    const float* __restrict__ Wo, float* __restrict__ out)
{
    __shared__ float As[128][40];
    __shared__ float Bs[32][72];

    const int tid = threadIdx.x;
    const int wid = tid >> 5;
    const int warp_m = wid >> 1;
    const int warp_n = wid & 1;
    const int m0 = blockIdx.x * 128;
    const int n0 = blockIdx.y * 64;

    wmma::fragment<wmma::accumulator, 16, 16, 8, float> acc[2][2];
    #pragma unroll
    for (int mi = 0; mi < 2; mi++)
        #pragma unroll
        for (int ni = 0; ni < 2; ni++)
            wmma::fill_fragment(acc[mi][ni], 0.0f);

    for (int k0 = 0; k0 < DOUTC; k0 += 32) {
        #pragma unroll
        for (int r = 0; r < 4; r++) {
            int f4 = tid + 256 * r;
            int m  = f4 >> 3;
            int kk = (f4 & 7) << 2;
            float4 v = *(const float4*)(g_ctx + (size_t)(m0 + m) * DOUTC + k0 + kk);
            *(float4*)(&As[m][kk]) = v;
        }
        #pragma unroll
        for (int r = 0; r < 2; r++) {
            int f4 = tid + 256 * r;
            int kk = f4 >> 4;
            int n  = (f4 & 15) << 2;
            float4 v = *(const float4*)(Wo + (size_t)(k0 + kk) * DOUTC + n0 + n);
            *(float4*)(&Bs[kk][n]) = v;
        }
        __syncthreads();
        #pragma unroll
        for (int ks = 0; ks < 4; ks++) {
            wmma::fragment<wmma::matrix_a, 16, 16, 8, wmma::precision::tf32, wmma::row_major> af[2];
            wmma::fragment<wmma::matrix_b, 16, 16, 8, wmma::precision::tf32, wmma::row_major> bf[2];
            #pragma unroll
            for (int mi = 0; mi < 2; mi++) {
                wmma::load_matrix_sync(af[mi], &As[warp_m * 32 + mi * 16][ks * 8], 40);
                #pragma unroll
                for (int t = 0; t < af[mi].num_elements; t++)
                    af[mi].x[t] = wmma::__float_to_tf32(af[mi].x[t]);
            }
            #pragma unroll
            for (int ni = 0; ni < 2; ni++) {
                wmma::load_matrix_sync(bf[ni], &Bs[ks * 8][warp_n * 32 + ni * 16], 72);
                #pragma unroll
                for (int t = 0; t < bf[ni].num_elements; t++)
                    bf[ni].x[t] = wmma::__float_to_tf32(bf[ni].x[t]);
            }
            #pragma unroll
            for (int mi = 0; mi < 2; mi++)
                #pragma unroll
                for (int ni = 0; ni < 2; ni++)
                    wmma::mma_sync(acc[mi][ni], af[mi], bf[ni], acc[mi][ni]);
        }
        __syncthreads();
    }

    #pragma unroll
    for (int mi = 0; mi < 2; mi++)
        #pragma unroll
        for (int ni = 0; ni < 2; ni++)
            wmma::store_matrix_sync(
                out + (size_t)(m0 + warp_m * 32 + mi * 16) * DOUTC + n0 + warp_n * 32 + ni * 16,
                acc[mi][ni], DOUTC, wmma::mem_row_major);
}

__global__ __launch_bounds__(256) void bias_add(float* __restrict__ out,
                                                const float* __restrict__ bo)
{
    int i4 = blockIdx.x * blockDim.x + threadIdx.x;   // over 8192*1024/4
    float4 v = ((float4*)out)[i4];
    const float4 bb = ((const float4*)bo)[i4 & 255];
    v.x += bb.x; v.y += bb.y; v.z += bb.z; v.w += bb.w;
    ((float4*)out)[i4] = v;
}

// ---------------------------------------------------------------------------
extern "C" void kernel_launch(void* const* d_in, const int* in_sizes, int n_in,
                              void* d_out, int out_size)
{
    const float* x  = (const float*)d_in[0];
    const int*   am = (const int*)  d_in[1];
    const float* Wq = (const float*)d_in[2];
    const float* Wk = (const float*)d_in[3];
    const float* Wv = (const float*)d_in[4];
    const float* Wo = (const float*)d_in[5];
    const float* bo = (const float*)d_in[6];
    float* out = (float*)d_out;

    cudaFuncSetAttribute(attn_kernel,
                         cudaFuncAttributeMaxDynamicSharedMemorySize,
                         ATTN_SMEM_BYTES);

    qkv_gemm<<<dim3(BB * NN / 128, HH, 3), 256>>>(x, Wq, Wk, Wv);
    attn_kernel<<<dim3(NN / 64, BB * HH), 256, ATTN_SMEM_BYTES>>>(am);
    out_gemm<<<dim3(BB * NN / 128, DOUTC / 64), 256>>>(Wo, out);
    bias_add<<<(BB * NN * DOUTC / 4) / 256, 256>>>(out, bo);
}

// round 5
// speedup vs baseline: 1.6017x; 1.6017x over previous
#include <cuda_runtime.h>
#include <mma.h>
#include <math.h>
#include <stdint.h>

using namespace nvcuda;

#define BB    4
#define NN    2048
#define DIN   1024
#define DOUTC 1024
#define HH    16
#define HD    64

// ---- scratch (__device__ globals; no allocs allowed) ----
__device__ float g_xr[BB*NN*DIN];        // tf32-rounded x
__device__ float g_wq[DIN*DOUTC];
__device__ float g_wk[DIN*DOUTC];
__device__ float g_wv[DIN*DOUTC];
__device__ float g_wo[DOUTC*DOUTC];
__device__ float g_q [BB*HH*NN*HD];      // [b,h,n,d] tf32-rounded
__device__ float g_k [BB*HH*NN*HD];
__device__ float g_v [BB*HH*NN*HD];
__device__ float g_ctx[BB*NN*DOUTC];     // [b,n,h*64+d] tf32-rounded

// ---- helpers ----
// NOTE: tf32 cvt destination must be a .b32 register ("=r"), not .f32.
__device__ __forceinline__ float rtf(float x) {
    uint32_t y;
    asm("cvt.rna.tf32.f32 %0, %1;" : "=r"(y) : "f"(x));
    return __uint_as_float(y);
}
__device__ __forceinline__ void cp16(void* smem_dst, const void* gsrc) {
    uint32_t d = (uint32_t)__cvta_generic_to_shared(smem_dst);
    asm volatile("cp.async.cg.shared.global [%0], [%1], 16;" :: "r"(d), "l"(gsrc));
}
#define CP_COMMIT()  asm volatile("cp.async.commit_group;")
#define CP_WAIT(N)   asm volatile("cp.async.wait_group %0;" :: "n"(N))

__device__ __forceinline__ void mma_tf32(float c[4], const float a[4], float b0, float b1) {
    asm volatile(
        "mma.sync.aligned.m16n8k8.row.col.f32.tf32.tf32.f32 "
        "{%0,%1,%2,%3},{%4,%5,%6,%7},{%8,%9},{%0,%1,%2,%3};"
        : "+f"(c[0]), "+f"(c[1]), "+f"(c[2]), "+f"(c[3])
        : "r"(__float_as_uint(a[0])), "r"(__float_as_uint(a[1])),
          "r"(__float_as_uint(a[2])), "r"(__float_as_uint(a[3])),
          "r"(__float_as_uint(b0)),  "r"(__float_as_uint(b1)));
}

// ---------------------------------------------------------------------------
// Pre-round fp32 -> tf32 (grid-stride over float4)
// ---------------------------------------------------------------------------
__global__ void round_k(const float4* __restrict__ src, float4* __restrict__ dst, int n4) {
    for (int i = blockIdx.x * blockDim.x + threadIdx.x; i < n4; i += gridDim.x * blockDim.x) {
        float4 v = src[i];
        v.x = rtf(v.x); v.y = rtf(v.y); v.z = rtf(v.z); v.w = rtf(v.w);
        dst[i] = v;
    }
}

// ---------------------------------------------------------------------------
// QKV GEMM: 128x128 block tile, BK=32, double-buffered cp.async.
// 8 warps (4x2): warp tile 32x64 (2x4 wmma m16n16k8). Inputs pre-rounded.
// z selects Q/K/V; output head-major [b,h,n,64], rounded to tf32.
// ---------------------------------------------------------------------------
#define ALDA 40
#define BLDB 132
#define GEMM_SMEM ((2*128*ALDA + 2*32*BLDB) * 4)

__global__ __launch_bounds__(256, 2) void qkv_gemm(void) {
    extern __shared__ float sg[];
    float* As = sg;                      // [2][128][ALDA]
    float* Bs = sg + 2 * 128 * ALDA;     // [2][32][BLDB]
#define AS(s,m,k) As[(((s)*128)+(m))*ALDA + (k)]
#define BS(s,k,n) Bs[(((s)*32)+(k))*BLDB + (n)]

    const int tid = threadIdx.x;
    const int wid = tid >> 5;
    const int warp_m = wid >> 1;    // 0..3 -> 32 rows
    const int warp_n = wid & 1;     // 0..1 -> 64 cols
    const int m0 = blockIdx.x * 128;
    const int n0 = blockIdx.y * 128;
    const int z  = blockIdx.z;

    const float* x = g_xr;
    const float* W = (z == 0) ? g_wq : ((z == 1) ? g_wk : g_wv);
    float* outb    = (z == 0) ? g_q  : ((z == 1) ? g_k  : g_v);

    wmma::fragment<wmma::accumulator, 16, 16, 8, float> acc[2][4];
    #pragma unroll
    for (int mi = 0; mi < 2; mi++)
        #pragma unroll
        for (int ni = 0; ni < 4; ni++)
            wmma::fill_fragment(acc[mi][ni], 0.0f);

    auto load_stage = [&](int s, int k0) {
        #pragma unroll
        for (int r = 0; r < 4; r++) {           // A: 1024 f4
            int f4 = tid + 256 * r;
            int m  = f4 >> 3;
            int kk = (f4 & 7) << 2;
            cp16(&AS(s, m, kk), x + (size_t)(m0 + m) * DIN + k0 + kk);
        }
        #pragma unroll
        for (int r = 0; r < 4; r++) {           // B: 1024 f4
            int f4 = tid + 256 * r;
            int kk = f4 >> 5;
            int n  = (f4 & 31) << 2;
            cp16(&BS(s, kk, n), W + (size_t)(k0 + kk) * DOUTC + n0 + n);
        }
        CP_COMMIT();
    };

    load_stage(0, 0);
    const int KT = DIN / 32;
    for (int kt = 0; kt < KT; kt++) {
        if (kt + 1 < KT) { load_stage((kt + 1) & 1, (kt + 1) * 32); CP_WAIT(1); }
        else             { CP_WAIT(0); }
        __syncthreads();
        const int s = kt & 1;
        #pragma unroll
        for (int ks = 0; ks < 4; ks++) {
            wmma::fragment<wmma::matrix_a, 16, 16, 8, wmma::precision::tf32, wmma::row_major> af[2];
            wmma::fragment<wmma::matrix_b, 16, 16, 8, wmma::precision::tf32, wmma::row_major> bf[4];
            #pragma unroll
            for (int mi = 0; mi < 2; mi++)
                wmma::load_matrix_sync(af[mi], &AS(s, warp_m * 32 + mi * 16, ks * 8), ALDA);
            #pragma unroll
            for (int ni = 0; ni < 4; ni++)
                wmma::load_matrix_sync(bf[ni], &BS(s, ks * 8, warp_n * 64 + ni * 16), BLDB);
            #pragma unroll
            for (int mi = 0; mi < 2; mi++)
                #pragma unroll
                for (int ni = 0; ni < 4; ni++)
                    wmma::mma_sync(acc[mi][ni], af[mi], bf[ni], acc[mi][ni]);
        }
        __syncthreads();
    }

    // store head-major, tf32-rounded
    const int b    = m0 / NN;
    const int nb   = m0 % NN;
    const int head = blockIdx.y * 2 + warp_n;
    #pragma unroll
    for (int mi = 0; mi < 2; mi++)
        #pragma unroll
        for (int ni = 0; ni < 4; ni++) {
            #pragma unroll
            for (int t = 0; t < acc[mi][ni].num_elements; t++)
                acc[mi][ni].x[t] = rtf(acc[mi][ni].x[t]);
            float* p = outb + ((size_t)(b * HH + head) * NN + nb + warp_m * 32 + mi * 16) * HD + ni * 16;
            wmma::store_matrix_sync(p, acc[mi][ni], HD, wmma::mem_row_major);
        }
}

// ---------------------------------------------------------------------------
// Flash attention v2: raw mma.m16n8k8.tf32, O accumulator in registers.
// Block = 128 q rows x (64-key tiles), 8 warps, each warp owns 16 q rows.
// Softmax fully in registers (quad shuffles). 2 barriers per k-tile.
// smem: sK[64][68], sVt[64][68] (V transposed), sP[8][16][68], mask[64].
// ---------------------------------------------------------------------------
#define ALD 68
#define ATTN_SMEM ((64*ALD*2 + 8*16*ALD) * 4 + 64 * 4)

__global__ __launch_bounds__(256, 2) void attn2(const int* __restrict__ amask) {
    extern __shared__ float sm[];
    float* sK  = sm;
    float* sVt = sK + 64 * ALD;
    float* sP  = sVt + 64 * ALD;              // [8][16*ALD]
    int*   sMask = (int*)(sP + 8 * 16 * ALD);

    const int tid  = threadIdx.x;
    const int w    = tid >> 5;
    const int lane = tid & 31;
    const int g    = lane >> 2;   // group (row within 16-tile)
    const int t    = lane & 3;    // thread-in-group
    const int qt   = gridDim.x - 1 - blockIdx.x;   // long blocks first
    const int bh   = blockIdx.y;
    const int b    = bh >> 4;
    const int h    = bh & 15;
    const int q0   = qt * 128;
    const int qrow = q0 + w * 16;
    float* sPw = sP + w * 16 * ALD;

    const float* kb = g_k + (size_t)bh * NN * HD;
    const float* vb = g_v + (size_t)bh * NN * HD;

    // Q fragments (registers, loop-invariant). A layout m16n8k8:
    // a0:(g, t) a1:(g+8, t) a2:(g, t+4) a3:(g+8, t+4), cols offset by kc*8.
    float qa[8][4];
    {
        const float* r0p = g_q + ((size_t)bh * NN + qrow + g)     * HD;
        const float* r1p = g_q + ((size_t)bh * NN + qrow + g + 8) * HD;
        #pragma unroll
        for (int kc = 0; kc < 8; kc++) {
            qa[kc][0] = r0p[kc * 8 + t];
            qa[kc][1] = r1p[kc * 8 + t];
            qa[kc][2] = r0p[kc * 8 + t + 4];
            qa[kc][3] = r1p[kc * 8 + t + 4];
        }
    }

    float o[8][4];
    #pragma unroll
    for (int nt = 0; nt < 8; nt++) { o[nt][0]=0.f; o[nt][1]=0.f; o[nt][2]=0.f; o[nt][3]=0.f; }
    float m0 = -INFINITY, m1 = -INFINITY, l0 = 0.f, l1 = 0.f;
    const int row0 = qrow + g, row1 = qrow + g + 8;

    const int ktmax = 2 * qt + 1;
    for (int kt = 0; kt <= ktmax; kt++) {
        const int kk0 = kt * 64;
        // K tile (row-major) — coalesced f4
        #pragma unroll
        for (int r = 0; r < 4; r++) {
            int f4  = tid + 256 * r;
            int key = f4 >> 4;
            int d   = (f4 & 15) << 2;
            *(float4*)&sK[key * ALD + d] =
                *(const float4*)(kb + (size_t)(kk0 + key) * HD + d);
        }
        // V tile transposed: sVt[hd][key]
        #pragma unroll
        for (int r = 0; r < 4; r++) {
            int key = tid >> 2;
            int dd  = ((tid & 3) + r * 4) << 2;
            float4 v = *(const float4*)(vb + (size_t)(kk0 + key) * HD + dd);
            sVt[(dd + 0) * ALD + key] = v.x;
            sVt[(dd + 1) * ALD + key] = v.y;
            sVt[(dd + 2) * ALD + key] = v.z;
            sVt[(dd + 3) * ALD + key] = v.w;
        }
        if (tid < 64) sMask[tid] = amask[b * NN + kk0 + tid];
        __syncthreads();

        // S = Q K^T  (B frag: b0=(k:t, n:g), b1=(k:t+4, n:g); K^T[k=hd][n=key])
        float s[8][4];
        #pragma unroll
        for (int nt = 0; nt < 8; nt++) { s[nt][0]=0.f; s[nt][1]=0.f; s[nt][2]=0.f; s[nt][3]=0.f; }
        #pragma unroll
        for (int kc = 0; kc < 8; kc++) {
            #pragma unroll
            for (int nt = 0; nt < 8; nt++) {
                float b0 = sK[(nt * 8 + g) * ALD + kc * 8 + t];
                float b1 = sK[(nt * 8 + g) * ALD + kc * 8 + t + 4];
                mma_tf32(s[nt], qa[kc], b0, b1);
            }
        }

        // scale + mask + register softmax (C layout: c0,c1 row=g cols 2t,2t+1; c2,c3 row=g+8)
        float mx0 = -1e30f, mx1 = -1e30f;
        #pragma unroll
        for (int nt = 0; nt < 8; nt++) {
            int j0 = nt * 8 + 2 * t, j1 = j0 + 1;
            bool mj0 = sMask[j0] != 0, mj1 = sMask[j1] != 0;
            s[nt][0] = (mj0 && (kk0 + j0 <= row0)) ? s[nt][0] * 0.125f : -1e30f;
            s[nt][1] = (mj1 && (kk0 + j1 <= row0)) ? s[nt][1] * 0.125f : -1e30f;
            s[nt][2] = (mj0 && (kk0 + j0 <= row1)) ? s[nt][2] * 0.125f : -1e30f;
            s[nt][3] = (mj1 && (kk0 + j1 <= row1)) ? s[nt][3] * 0.125f : -1e30f;
            mx0 = fmaxf(mx0, fmaxf(s[nt][0], s[nt][1]));
            mx1 = fmaxf(mx1, fmaxf(s[nt][2], s[nt][3]));
        }
        mx0 = fmaxf(mx0, __shfl_xor_sync(0xffffffffu, mx0, 1));
        mx0 = fmaxf(mx0, __shfl_xor_sync(0xffffffffu, mx0, 2));
        mx1 = fmaxf(mx1, __shfl_xor_sync(0xffffffffu, mx1, 1));
        mx1 = fmaxf(mx1, __shfl_xor_sync(0xffffffffu, mx1, 2));

        const float mn0 = fmaxf(m0, mx0), mn1 = fmaxf(m1, mx1);
        const float al0 = __expf(m0 - mn0), al1 = __expf(m1 - mn1);
        m0 = mn0; m1 = mn1;

        float sum0 = 0.f, sum1 = 0.f;
        #pragma unroll
        for (int nt = 0; nt < 8; nt++) {
            s[nt][0] = __expf(s[nt][0] - mn0);
            s[nt][1] = __expf(s[nt][1] - mn0);
            s[nt][2] = __expf(s[nt][2] - mn1);
            s[nt][3] = __expf(s[nt][3] - mn1);
            sum0 += s[nt][0] + s[nt][1];
            sum1 += s[nt][2] + s[nt][3];
        }
        sum0 += __shfl_xor_sync(0xffffffffu, sum0, 1);
        sum0 += __shfl_xor_sync(0xffffffffu, sum0, 2);
        sum1 += __shfl_xor_sync(0xffffffffu, sum1, 1);
        sum1 += __shfl_xor_sync(0xffffffffu, sum1, 2);
        l0 = l0 * al0 + sum0;
        l1 = l1 * al1 + sum1;

        // rescale O, stage P (tf32-rounded) into warp-private smem
        #pragma unroll
        for (int nt = 0; nt < 8; nt++) {
            o[nt][0] *= al0; o[nt][1] *= al0; o[nt][2] *= al1; o[nt][3] *= al1;
            int j0 = nt * 8 + 2 * t;
            sPw[g * ALD + j0]           = rtf(s[nt][0]);
            sPw[g * ALD + j0 + 1]       = rtf(s[nt][1]);
            sPw[(g + 8) * ALD + j0]     = rtf(s[nt][2]);
            sPw[(g + 8) * ALD + j0 + 1] = rtf(s[nt][3]);
        }
        __syncwarp();

        // O += P @ V   (A from sPw in A-layout, B from sVt[hd][key])
        #pragma unroll
        for (int kc = 0; kc < 8; kc++) {
            float av[4];
            av[0] = sPw[g * ALD + kc * 8 + t];
            av[1] = sPw[(g + 8) * ALD + kc * 8 + t];
            av[2] = sPw[g * ALD + kc * 8 + t + 4];
            av[3] = sPw[(g + 8) * ALD + kc * 8 + t + 4];
            #pragma unroll
            for (int nt = 0; nt < 8; nt++) {
                float b0 = sVt[(nt * 8 + g) * ALD + kc * 8 + t];
                float b1 = sVt[(nt * 8 + g) * ALD + kc * 8 + t + 4];
                mma_tf32(o[nt], av, b0, b1);
            }
        }
        __syncthreads();
    }

    // normalize, round, stage in sPw, coalesced f4 store to ctx
    const float il0 = 1.0f / l0, il1 = 1.0f / l1;
    #pragma unroll
    for (int nt = 0; nt < 8; nt++) {
        int j0 = nt * 8 + 2 * t;
        sPw[g * ALD + j0]           = rtf(o[nt][0] * il0);
        sPw[g * ALD + j0 + 1]       = rtf(o[nt][1] * il0);
        sPw[(g + 8) * ALD + j0]     = rtf(o[nt][2] * il1);
        sPw[(g + 8) * ALD + j0 + 1] = rtf(o[nt][3] * il1);
    }
    __syncwarp();
    float* cb = g_ctx + ((size_t)b * NN + qrow) * DOUTC + h * HD;
    #pragma unroll
    for (int r = 0; r < 8; r++) {
        int f4  = lane + 32 * r;       // 256 f4 = 16 rows x 16 f4
        int row = f4 >> 4;
        int d4  = (f4 & 15) << 2;
        *(float4*)(cb + (size_t)row * DOUTC + d4) = *(float4*)&sPw[row * ALD + d4];
    }
}

// ---------------------------------------------------------------------------
// Output projection: out = ctx @ Wo  (both pre-rounded), 128x128 tiles.
// ---------------------------------------------------------------------------
__global__ __launch_bounds__(256, 2) void out_gemm(float* __restrict__ out) {
    extern __shared__ float sg[];
    float* As = sg;
    float* Bs = sg + 2 * 128 * ALDA;

    const int tid = threadIdx.x;
    const int wid = tid >> 5;
    const int warp_m = wid >> 1;
    const int warp_n = wid & 1;
    const int m0 = blockIdx.x * 128;
    const int n0 = blockIdx.y * 128;

    wmma::fragment<wmma::accumulator, 16, 16, 8, float> acc[2][4];
    #pragma unroll
    for (int mi = 0; mi < 2; mi++)
        #pragma unroll
        for (int ni = 0; ni < 4; ni++)
            wmma::fill_fragment(acc[mi][ni], 0.0f);

    auto load_stage = [&](int s, int k0) {
        #pragma unroll
        for (int r = 0; r < 4; r++) {
            int f4 = tid + 256 * r;
            int m  = f4 >> 3;
            int kk = (f4 & 7) << 2;
            cp16(&AS(s, m, kk), g_ctx + (size_t)(m0 + m) * DOUTC + k0 + kk);
        }
        #pragma unroll
        for (int r = 0; r < 4; r++) {
            int f4 = tid + 256 * r;
            int kk = f4 >> 5;
            int n  = (f4 & 31) << 2;
            cp16(&BS(s, kk, n), g_wo + (size_t)(k0 + kk) * DOUTC + n0 + n);
        }
        CP_COMMIT();
    };

    load_stage(0, 0);
    const int KT = DOUTC / 32;
    for (int kt = 0; kt < KT; kt++) {
        if (kt + 1 < KT) { load_stage((kt + 1) & 1, (kt + 1) * 32); CP_WAIT(1); }
        else             { CP_WAIT(0); }
        __syncthreads();
        const int s = kt & 1;
        #pragma unroll
        for (int ks = 0; ks < 4; ks++) {
            wmma::fragment<wmma::matrix_a, 16, 16, 8, wmma::precision::tf32, wmma::row_major> af[2];
            wmma::fragment<wmma::matrix_b, 16, 16, 8, wmma::precision::tf32, wmma::row_major> bf[4];
            #pragma unroll
            for (int mi = 0; mi < 2; mi++)
                wmma::load_matrix_sync(af[mi], &AS(s, warp_m * 32 + mi * 16, ks * 8), ALDA);
            #pragma unroll
            for (int ni = 0; ni < 4; ni++)
                wmma::load_matrix_sync(bf[ni], &BS(s, ks * 8, warp_n * 64 + ni * 16), BLDB);
            #pragma unroll
            for (int mi = 0; mi < 2; mi++)
                #pragma unroll
                for (int ni = 0; ni < 4; ni++)
                    wmma::mma_sync(acc[mi][ni], af[mi], bf[ni], acc[mi][ni]);
        }
        __syncthreads();
    }

    #pragma unroll
    for (int mi = 0; mi < 2; mi++)
        #pragma unroll
        for (int ni = 0; ni < 4; ni++)
            wmma::store_matrix_sync(
                out + (size_t)(m0 + warp_m * 32 + mi * 16) * DOUTC + n0 + warp_n * 64 + ni * 16,
                acc[mi][ni], DOUTC, wmma::mem_row_major);
}

__global__ __launch_bounds__(256) void bias_add(float* __restrict__ out,
                                                const float* __restrict__ bo) {
    int i4 = blockIdx.x * blockDim.x + threadIdx.x;
    float4 v = ((float4*)out)[i4];
    const float4 bb = ((const float4*)bo)[i4 & 255];
    v.x += bb.x; v.y += bb.y; v.z += bb.z; v.w += bb.w;
    ((float4*)out)[i4] = v;
}

// ---------------------------------------------------------------------------
extern "C" void kernel_launch(void* const* d_in, const int* in_sizes, int n_in,
                              void* d_out, int out_size) {
    const float* x  = (const float*)d_in[0];
    const int*   am = (const int*)  d_in[1];
    const float* Wq = (const float*)d_in[2];
    const float* Wk = (const float*)d_in[3];
    const float* Wv = (const float*)d_in[4];
    const float* Wo = (const float*)d_in[5];
    const float* bo = (const float*)d_in[6];
    float* out = (float*)d_out;

    // No static caching (harness forbids static guards) — these host calls are
    // idempotent, stream-free, and capture-legal.
    float *p_xr, *p_wq, *p_wk, *p_wv, *p_wo;
    cudaGetSymbolAddress((void**)&p_xr, g_xr);
    cudaGetSymbolAddress((void**)&p_wq, g_wq);
    cudaGetSymbolAddress((void**)&p_wk, g_wk);
    cudaGetSymbolAddress((void**)&p_wv, g_wv);
    cudaGetSymbolAddress((void**)&p_wo, g_wo);
    cudaFuncSetAttribute(qkv_gemm, cudaFuncAttributeMaxDynamicSharedMemorySize, GEMM_SMEM);
    cudaFuncSetAttribute(out_gemm, cudaFuncAttributeMaxDynamicSharedMemorySize, GEMM_SMEM);
    cudaFuncSetAttribute(attn2,    cudaFuncAttributeMaxDynamicSharedMemorySize, ATTN_SMEM);

    round_k<<<512, 256>>>((const float4*)x,  (float4*)p_xr, BB*NN*DIN/4);
    round_k<<<256, 256>>>((const float4*)Wq, (float4*)p_wq, DIN*DOUTC/4);
    round_k<<<256, 256>>>((const float4*)Wk, (float4*)p_wk, DIN*DOUTC/4);
    round_k<<<256, 256>>>((const float4*)Wv, (float4*)p_wv, DIN*DOUTC/4);
    round_k<<<256, 256>>>((const float4*)Wo, (float4*)p_wo, DOUTC*DOUTC/4);

    qkv_gemm<<<dim3(BB * NN / 128, DOUTC / 128, 3), 256, GEMM_SMEM>>>();
    attn2<<<dim3(NN / 128, BB * HH), 256, ATTN_SMEM>>>(am);
    out_gemm<<<dim3(BB * NN / 128, DOUTC / 128), 256, GEMM_SMEM>>>(out);
    bias_add<<<(BB * NN * DOUTC / 4) / 256, 256>>>(out, bo);
}

// round 8
// speedup vs baseline: 1.6152x; 1.0084x over previous
#include <cuda_runtime.h>
#include <mma.h>
#include <math.h>
#include <stdint.h>

using namespace nvcuda;

#define BB    4
#define NN    2048
#define DIN   1024
#define DOUTC 1024
#define HH    16
#define HD    64

// ---- scratch (__device__ globals; no allocs allowed) ----
__device__ float g_xr[BB*NN*DIN];        // tf32-rounded x
__device__ float g_wq[DIN*DOUTC];
__device__ float g_wk[DIN*DOUTC];
__device__ float g_wv[DIN*DOUTC];
__device__ float g_wo[DOUTC*DOUTC];
__device__ float g_q [BB*HH*NN*HD];      // [b,h,n,d] tf32-rounded
__device__ float g_k [BB*HH*NN*HD];
__device__ float g_v [BB*HH*NN*HD];
__device__ float g_ctx[BB*NN*DOUTC];     // [b,n,h*64+d] tf32-rounded
__device__ int   g_len[BB];              // per-batch valid length

// ---- helpers ----
__device__ __forceinline__ float rtf(float x) {
    uint32_t y;
    asm("cvt.rna.tf32.f32 %0, %1;" : "=r"(y) : "f"(x));
    return __uint_as_float(y);
}
__device__ __forceinline__ void cp16(void* smem_dst, const void* gsrc) {
    uint32_t d = (uint32_t)__cvta_generic_to_shared(smem_dst);
    asm volatile("cp.async.cg.shared.global [%0], [%1], 16;" :: "r"(d), "l"(gsrc));
}
#define CP_COMMIT()  asm volatile("cp.async.commit_group;")
#define CP_WAIT(N)   asm volatile("cp.async.wait_group %0;" :: "n"(N))

__device__ __forceinline__ void mma_tf32(float c[4], const float a[4], float b0, float b1) {
    asm volatile(
        "mma.sync.aligned.m16n8k8.row.col.f32.tf32.tf32.f32 "
        "{%0,%1,%2,%3},{%4,%5,%6,%7},{%8,%9},{%0,%1,%2,%3};"
        : "+f"(c[0]), "+f"(c[1]), "+f"(c[2]), "+f"(c[3])
        : "r"(__float_as_uint(a[0])), "r"(__float_as_uint(a[1])),
          "r"(__float_as_uint(a[2])), "r"(__float_as_uint(a[3])),
          "r"(__float_as_uint(b0)),  "r"(__float_as_uint(b1)));
}

// ---------------------------------------------------------------------------
// Fused tf32 pre-rounding for all 5 input tensors. blockIdx.y = segment.
// ---------------------------------------------------------------------------
__global__ void round_all(const float4* __restrict__ x,  const float4* __restrict__ wq,
                          const float4* __restrict__ wk, const float4* __restrict__ wv,
                          const float4* __restrict__ wo) {
    const int seg = blockIdx.y;
    const float4* src; float4* dst; int n4;
    if      (seg == 0) { src = x;  dst = (float4*)g_xr; n4 = BB*NN*DIN/4;  }
    else if (seg == 1) { src = wq; dst = (float4*)g_wq; n4 = DIN*DOUTC/4;  }
    else if (seg == 2) { src = wk; dst = (float4*)g_wk; n4 = DIN*DOUTC/4;  }
    else if (seg == 3) { src = wv; dst = (float4*)g_wv; n4 = DIN*DOUTC/4;  }
    else               { src = wo; dst = (float4*)g_wo; n4 = DOUTC*DOUTC/4; }
    for (int i = blockIdx.x * blockDim.x + threadIdx.x; i < n4; i += gridDim.x * blockDim.x) {
        float4 v = src[i];
        v.x = rtf(v.x); v.y = rtf(v.y); v.z = rtf(v.z); v.w = rtf(v.w);
        dst[i] = v;
    }
}

// Per-batch valid length = sum of right-padded mask row.
__global__ void len_k(const int* __restrict__ am) {
    __shared__ int red[8];
    const int b = blockIdx.x;
    int s = 0;
    for (int i = threadIdx.x; i < NN; i += 256) s += am[b * NN + i];
    #pragma unroll
    for (int o = 16; o; o >>= 1) s += __shfl_xor_sync(0xffffffffu, s, o);
    if ((threadIdx.x & 31) == 0) red[threadIdx.x >> 5] = s;
    __syncthreads();
    if (threadIdx.x < 8) {
        int v = red[threadIdx.x];
        #pragma unroll
        for (int o = 4; o; o >>= 1) v += __shfl_xor_sync(0xffu, v, o);
        if (threadIdx.x == 0) g_len[b] = v;
    }
}

// ---------------------------------------------------------------------------
// QKV GEMM: 128x128 block tile, BK=32, double-buffered cp.async.
// 8 warps (4x2): warp tile 32x64 (2x4 wmma m16n16k8). Inputs pre-rounded.
// z selects Q/K/V; output head-major [b,h,n,64], rounded to tf32.
// ---------------------------------------------------------------------------
#define ALDA 40
#define BLDB 132
#define GEMM_SMEM ((2*128*ALDA + 2*32*BLDB) * 4)

__global__ __launch_bounds__(256, 2) void qkv_gemm(void) {
    extern __shared__ float sg[];
    float* As = sg;                      // [2][128][ALDA]
    float* Bs = sg + 2 * 128 * ALDA;     // [2][32][BLDB]
#define AS(s,m,k) As[(((s)*128)+(m))*ALDA + (k)]
#define BS(s,k,n) Bs[(((s)*32)+(k))*BLDB + (n)]

    const int tid = threadIdx.x;
    const int wid = tid >> 5;
    const int warp_m = wid >> 1;
    const int warp_n = wid & 1;
    const int m0 = blockIdx.x * 128;
    const int n0 = blockIdx.y * 128;
    const int z  = blockIdx.z;

    const float* x = g_xr;
    const float* W = (z == 0) ? g_wq : ((z == 1) ? g_wk : g_wv);
    float* outb    = (z == 0) ? g_q  : ((z == 1) ? g_k  : g_v);

    wmma::fragment<wmma::accumulator, 16, 16, 8, float> acc[2][4];
    #pragma unroll
    for (int mi = 0; mi < 2; mi++)
        #pragma unroll
        for (int ni = 0; ni < 4; ni++)
            wmma::fill_fragment(acc[mi][ni], 0.0f);

    auto load_stage = [&](int s, int k0) {
        #pragma unroll
        for (int r = 0; r < 4; r++) {
            int f4 = tid + 256 * r;
            int m  = f4 >> 3;
            int kk = (f4 & 7) << 2;
            cp16(&AS(s, m, kk), x + (size_t)(m0 + m) * DIN + k0 + kk);
        }
        #pragma unroll
        for (int r = 0; r < 4; r++) {
            int f4 = tid + 256 * r;
            int kk = f4 >> 5;
            int n  = (f4 & 31) << 2;
            cp16(&BS(s, kk, n), W + (size_t)(k0 + kk) * DOUTC + n0 + n);
        }
        CP_COMMIT();
    };

    load_stage(0, 0);
    const int KT = DIN / 32;
    for (int kt = 0; kt < KT; kt++) {
        if (kt + 1 < KT) { load_stage((kt + 1) & 1, (kt + 1) * 32); CP_WAIT(1); }
        else             { CP_WAIT(0); }
        __syncthreads();
        const int s = kt & 1;
        #pragma unroll
        for (int ks = 0; ks < 4; ks++) {
            wmma::fragment<wmma::matrix_a, 16, 16, 8, wmma::precision::tf32, wmma::row_major> af[2];
            wmma::fragment<wmma::matrix_b, 16, 16, 8, wmma::precision::tf32, wmma::row_major> bf[4];
            #pragma unroll
            for (int mi = 0; mi < 2; mi++)
                wmma::load_matrix_sync(af[mi], &AS(s, warp_m * 32 + mi * 16, ks * 8), ALDA);
            #pragma unroll
            for (int ni = 0; ni < 4; ni++)
                wmma::load_matrix_sync(bf[ni], &BS(s, ks * 8, warp_n * 64 + ni * 16), BLDB);
            #pragma unroll
            for (int mi = 0; mi < 2; mi++)
                #pragma unroll
                for (int ni = 0; ni < 4; ni++)
                    wmma::mma_sync(acc[mi][ni], af[mi], bf[ni], acc[mi][ni]);
        }
        __syncthreads();
    }

    const int b    = m0 / NN;
    const int nb   = m0 % NN;
    const int head = blockIdx.y * 2 + warp_n;
    #pragma unroll
    for (int mi = 0; mi < 2; mi++)
        #pragma unroll
        for (int ni = 0; ni < 4; ni++) {
            #pragma unroll
            for (int t = 0; t < acc[mi][ni].num_elements; t++)
                acc[mi][ni].x[t] = rtf(acc[mi][ni].x[t]);
            float* p = outb + ((size_t)(b * HH + head) * NN + nb + warp_m * 32 + mi * 16) * HD + ni * 16;
            wmma::store_matrix_sync(p, acc[mi][ni], HD, wmma::mem_row_major);
        }
}

// ---------------------------------------------------------------------------
// Flash attention v3: raw mma.m16n8k8.tf32, register O, cp.async double-buffered
// K/V (both row-major, LD=72 -> conflict-free fragment reads, no V transpose),
// per-batch length clamp to skip fully-padded key tiles.
// ---------------------------------------------------------------------------
#define KLD 72
#define ATTN_SMEM ((2*64*KLD*2 + 8*16*KLD) * 4 + 2*64*4)

__global__ __launch_bounds__(256, 2) void attn3(const int* __restrict__ amask) {
    extern __shared__ float sm[];
    float* sK = sm;                       // [2][64*KLD]  row-major [key][hd]
    float* sV = sK + 2 * 64 * KLD;        // [2][64*KLD]  row-major [key][hd]
    float* sP = sV + 2 * 64 * KLD;        // [8][16*KLD]  warp-private P / O staging
    int* sMask = (int*)(sP + 8 * 16 * KLD);  // [2][64]

    const int tid  = threadIdx.x;
    const int w    = tid >> 5;
    const int lane = tid & 31;
    const int g    = lane >> 2;
    const int t    = lane & 3;
    const int qt   = gridDim.x - 1 - blockIdx.x;   // heavy blocks first
    const int bh   = blockIdx.y;
    const int b    = bh >> 4;
    const int h    = bh & 15;
    const int q0   = qt * 128;
    const int qrow = q0 + w * 16;
    float* sPw = sP + w * 16 * KLD;

    const float* kb = g_k + (size_t)bh * NN * HD;
    const float* vb = g_v + (size_t)bh * NN * HD;
    const int len = g_len[b];

    // Q fragments, pre-scaled by 1/sqrt(64)=2^-3 (exact in tf32).
    float qa[8][4];
    {
        const float* r0p = g_q + ((size_t)bh * NN + qrow + g)     * HD;
        const float* r1p = g_q + ((size_t)bh * NN + qrow + g + 8) * HD;
        #pragma unroll
        for (int kc = 0; kc < 8; kc++) {
            qa[kc][0] = r0p[kc * 8 + t]     * 0.125f;
            qa[kc][1] = r1p[kc * 8 + t]     * 0.125f;
            qa[kc][2] = r0p[kc * 8 + t + 4] * 0.125f;
            qa[kc][3] = r1p[kc * 8 + t + 4] * 0.125f;
        }
    }

    float o[8][4];
    #pragma unroll
    for (int nt = 0; nt < 8; nt++) { o[nt][0]=0.f; o[nt][1]=0.f; o[nt][2]=0.f; o[nt][3]=0.f; }
    float m0 = -INFINITY, m1 = -INFINITY, l0 = 0.f, l1 = 0.f;
    const int row0 = qrow + g, row1 = qrow + g + 8;

    auto load_tile = [&](int s, int kt) {
        const float* kp = kb + (size_t)kt * 64 * HD;
        const float* vp = vb + (size_t)kt * 64 * HD;
        #pragma unroll
        for (int r = 0; r < 4; r++) {
            int f4  = tid + 256 * r;
            int key = f4 >> 4;
            int d   = (f4 & 15) << 2;
            cp16(&sK[(s * 64 + key) * KLD + d], kp + key * HD + d);
            cp16(&sV[(s * 64 + key) * KLD + d], vp + key * HD + d);
        }
        if (tid < 16) cp16(&sMask[s * 64 + tid * 4], amask + b * NN + kt * 64 + tid * 4);
        CP_COMMIT();
    };

    const int kend    = min(q0 + 128, len);
    const int n_tiles = (kend + 63) >> 6;

    load_tile(0, 0);
    for (int kt = 0; kt < n_tiles; kt++) {
        if (kt + 1 < n_tiles) { load_tile((kt + 1) & 1, kt + 1); CP_WAIT(1); }
        else                  { CP_WAIT(0); }
        __syncthreads();                         // tile kt visible to all warps
        const int s0 = kt & 1;
        const float* K = sK + s0 * 64 * KLD;
        const float* V = sV + s0 * 64 * KLD;
        const int*   M = sMask + s0 * 64;
        const int kk0 = kt * 64;

        // S = Qs K^T : b(k=hd, n=key) = K[key][hd]  (bank-free: 8g+t)
        float s[8][4];
        #pragma unroll
        for (int nt = 0; nt < 8; nt++) { s[nt][0]=0.f; s[nt][1]=0.f; s[nt][2]=0.f; s[nt][3]=0.f; }
        #pragma unroll
        for (int kc = 0; kc < 8; kc++) {
            #pragma unroll
            for (int nt = 0; nt < 8; nt++) {
                float b0 = K[(nt * 8 + g) * KLD + kc * 8 + t];
                float b1 = K[(nt * 8 + g) * KLD + kc * 8 + t + 4];
                mma_tf32(s[nt], qa[kc], b0, b1);
            }
        }

        // mask + register online softmax
        float mx0 = -1e30f, mx1 = -1e30f;
        #pragma unroll
        for (int nt = 0; nt < 8; nt++) {
            int j0 = nt * 8 + 2 * t, j1 = j0 + 1;
            bool mj0 = M[j0] != 0, mj1 = M[j1] != 0;
            s[nt][0] = (mj0 && (kk0 + j0 <= row0)) ? s[nt][0] : -1e30f;
            s[nt][1] = (mj1 && (kk0 + j1 <= row0)) ? s[nt][1] : -1e30f;
            s[nt][2] = (mj0 && (kk0 + j0 <= row1)) ? s[nt][2] : -1e30f;
            s[nt][3] = (mj1 && (kk0 + j1 <= row1)) ? s[nt][3] : -1e30f;
            mx0 = fmaxf(mx0, fmaxf(s[nt][0], s[nt][1]));
            mx1 = fmaxf(mx1, fmaxf(s[nt][2], s[nt][3]));
        }
        mx0 = fmaxf(mx0, __shfl_xor_sync(0xffffffffu, mx0, 1));
        mx0 = fmaxf(mx0, __shfl_xor_sync(0xffffffffu, mx0, 2));
        mx1 = fmaxf(mx1, __shfl_xor_sync(0xffffffffu, mx1, 1));
        mx1 = fmaxf(mx1, __shfl_xor_sync(0xffffffffu, mx1, 2));

        const float mn0 = fmaxf(m0, mx0), mn1 = fmaxf(m1, mx1);
        const float al0 = __expf(m0 - mn0), al1 = __expf(m1 - mn1);
        m0 = mn0; m1 = mn1;

        float sum0 = 0.f, sum1 = 0.f;
        #pragma unroll
        for (int nt = 0; nt < 8; nt++) {
            s[nt][0] = __expf(s[nt][0] - mn0);
            s[nt][1] = __expf(s[nt][1] - mn0);
            s[nt][2] = __expf(s[nt][2] - mn1);
            s[nt][3] = __expf(s[nt][3] - mn1);
            sum0 += s[nt][0] + s[nt][1];
            sum1 += s[nt][2] + s[nt][3];
        }
        sum0 += __shfl_xor_sync(0xffffffffu, sum0, 1);
        sum0 += __shfl_xor_sync(0xffffffffu, sum0, 2);
        sum1 += __shfl_xor_sync(0xffffffffu, sum1, 1);
        sum1 += __shfl_xor_sync(0xffffffffu, sum1, 2);
        l0 = l0 * al0 + sum0;
        l1 = l1 * al1 + sum1;

        // rescale O, stage P (tf32) into warp-private smem
        #pragma unroll
        for (int nt = 0; nt < 8; nt++) {
            o[nt][0] *= al0; o[nt][1] *= al0; o[nt][2] *= al1; o[nt][3] *= al1;
            int j0 = nt * 8 + 2 * t;
            sPw[g * KLD + j0]           = rtf(s[nt][0]);
            sPw[g * KLD + j0 + 1]       = rtf(s[nt][1]);
            sPw[(g + 8) * KLD + j0]     = rtf(s[nt][2]);
            sPw[(g + 8) * KLD + j0 + 1] = rtf(s[nt][3]);
        }
        __syncwarp();

        // O += P @ V : b(k=key, n=hd) = V[key][hd] (row-major, bank-free)
        #pragma unroll
        for (int kc = 0; kc < 8; kc++) {
            float av[4];
            av[0] = sPw[g * KLD + kc * 8 + t];
            av[1] = sPw[(g + 8) * KLD + kc * 8 + t];
            av[2] = sPw[g * KLD + kc * 8 + t + 4];
            av[3] = sPw[(g + 8) * KLD + kc * 8 + t + 4];
            #pragma unroll
            for (int nt = 0; nt < 8; nt++) {
                float b0 = V[(kc * 8 + t) * KLD + nt * 8 + g];
                float b1 = V[(kc * 8 + t + 4) * KLD + nt * 8 + g];
                mma_tf32(o[nt], av, b0, b1);
            }
        }
        __syncthreads();                         // buffer s0 free for reload
    }

    // normalize, round, stage, coalesced f4 store to ctx[b, n, h*64+d]
    const float il0 = 1.0f / l0, il1 = 1.0f / l1;
    #pragma unroll
    for (int nt = 0; nt < 8; nt++) {
        int j0 = nt * 8 + 2 * t;
        sPw[g * KLD + j0]           = rtf(o[nt][0] * il0);
        sPw[g * KLD + j0 + 1]       = rtf(o[nt][1] * il0);
        sPw[(g + 8) * KLD + j0]     = rtf(o[nt][2] * il1);
        sPw[(g + 8) * KLD + j0 + 1] = rtf(o[nt][3] * il1);
    }
    __syncwarp();
    float* cb = g_ctx + ((size_t)b * NN + qrow) * DOUTC + h * HD;
    #pragma unroll
    for (int r = 0; r < 8; r++) {
        int f4  = lane + 32 * r;
        int row = f4 >> 4;
        int d4  = (f4 & 15) << 2;
        *(float4*)(cb + (size_t)row * DOUTC + d4) = *(float4*)&sPw[row * KLD + d4];
    }
}

// ---------------------------------------------------------------------------
// Output projection: out = ctx @ Wo (both pre-rounded), 128x128 tiles.
// ---------------------------------------------------------------------------
__global__ __launch_bounds__(256, 2) void out_gemm(float* __restrict__ out) {
    extern __shared__ float sg[];
    float* As = sg;
    float* Bs = sg + 2 * 128 * ALDA;

    const int tid = threadIdx.x;
    const int wid = tid >> 5;
    const int warp_m = wid >> 1;
    const int warp_n = wid & 1;
    const int m0 = blockIdx.x * 128;
    const int n0 = blockIdx.y * 128;

    wmma::fragment<wmma::accumulator, 16, 16, 8, float> acc[2][4];
    #pragma unroll
    for (int mi = 0; mi < 2; mi++)
        #pragma unroll
        for (int ni = 0; ni < 4; ni++)
            wmma::fill_fragment(acc[mi][ni], 0.0f);

    auto load_stage = [&](int s, int k0) {
        #pragma unroll
        for (int r = 0; r < 4; r++) {
            int f4 = tid + 256 * r;
            int m  = f4 >> 3;
            int kk = (f4 & 7) << 2;
            cp16(&AS(s, m, kk), g_ctx + (size_t)(m0 + m) * DOUTC + k0 + kk);
        }
        #pragma unroll
        for (int r = 0; r < 4; r++) {
            int f4 = tid + 256 * r;
            int kk = f4 >> 5;
            int n  = (f4 & 31) << 2;
            cp16(&BS(s, kk, n), g_wo + (size_t)(k0 + kk) * DOUTC + n0 + n);
        }
        CP_COMMIT();
    };

    load_stage(0, 0);
    const int KT = DOUTC / 32;
    for (int kt = 0; kt < KT; kt++) {
        if (kt + 1 < KT) { load_stage((kt + 1) & 1, (kt + 1) * 32); CP_WAIT(1); }
        else             { CP_WAIT(0); }
        __syncthreads();
        const int s = kt & 1;
        #pragma unroll
        for (int ks = 0; ks < 4; ks++) {
            wmma::fragment<wmma::matrix_a, 16, 16, 8, wmma::precision::tf32, wmma::row_major> af[2];
            wmma::fragment<wmma::matrix_b, 16, 16, 8, wmma::precision::tf32, wmma::row_major> bf[4];
            #pragma unroll
            for (int mi = 0; mi < 2; mi++)
                wmma::load_matrix_sync(af[mi], &AS(s, warp_m * 32 + mi * 16, ks * 8), ALDA);
            #pragma unroll
            for (int ni = 0; ni < 4; ni++)
                wmma::load_matrix_sync(bf[ni], &BS(s, ks * 8, warp_n * 64 + ni * 16), BLDB);
            #pragma unroll
            for (int mi = 0; mi < 2; mi++)
                #pragma unroll
                for (int ni = 0; ni < 4; ni++)
                    wmma::mma_sync(acc[mi][ni], af[mi], bf[ni], acc[mi][ni]);
        }
        __syncthreads();
    }

    #pragma unroll
    for (int mi = 0; mi < 2; mi++)
        #pragma unroll
        for (int ni = 0; ni < 4; ni++)
            wmma::store_matrix_sync(
                out + (size_t)(m0 + warp_m * 32 + mi * 16) * DOUTC + n0 + warp_n * 64 + ni * 16,
                acc[mi][ni], DOUTC, wmma::mem_row_major);
}

__global__ __launch_bounds__(256) void bias_add(float* __restrict__ out,
                                                const float* __restrict__ bo) {
    int i4 = blockIdx.x * blockDim.x + threadIdx.x;
    float4 v = ((float4*)out)[i4];
    const float4 bb = ((const float4*)bo)[i4 & 255];
    v.x += bb.x; v.y += bb.y; v.z += bb.z; v.w += bb.w;
    ((float4*)out)[i4] = v;
}

// ---------------------------------------------------------------------------
extern "C" void kernel_launch(void* const* d_in, const int* in_sizes, int n_in,
                              void* d_out, int out_size) {
    const float* x  = (const float*)d_in[0];
    const int*   am = (const int*)  d_in[1];
    const float* Wq = (const float*)d_in[2];
    const float* Wk = (const float*)d_in[3];
    const float* Wv = (const float*)d_in[4];
    const float* Wo = (const float*)d_in[5];
    const float* bo = (const float*)d_in[6];
    float* out = (float*)d_out;

    cudaFuncSetAttribute(qkv_gemm, cudaFuncAttributeMaxDynamicSharedMemorySize, GEMM_SMEM);
    cudaFuncSetAttribute(out_gemm, cudaFuncAttributeMaxDynamicSharedMemorySize, GEMM_SMEM);
    cudaFuncSetAttribute(attn3,    cudaFuncAttributeMaxDynamicSharedMemorySize, ATTN_SMEM);

    round_all<<<dim3(512, 5), 256>>>((const float4*)x,  (const float4*)Wq,
                                     (const float4*)Wk, (const float4*)Wv,
                                     (const float4*)Wo);
    len_k<<<BB, 256>>>(am);
    qkv_gemm<<<dim3(BB * NN / 128, DOUTC / 128, 3), 256, GEMM_SMEM>>>();
    attn3<<<dim3(NN / 128, BB * HH), 256, ATTN_SMEM>>>(am);
    out_gemm<<<dim3(BB * NN / 128, DOUTC / 128), 256, GEMM_SMEM>>>(out);
    bias_add<<<(BB * NN * DOUTC / 4) / 256, 256>>>(out, bo);
}

// round 14
// speedup vs baseline: 4.7205x; 2.9226x over previous
#include <cuda_runtime.h>
#include <cuda_fp16.h>
#include <math.h>
#include <stdint.h>

#define BB    4
#define NN    2048
#define DIN   1024
#define DOUTC 1024
#define HH    16
#define HD    64

// ---- scratch (__device__ globals; no allocs allowed) ----
__device__ __align__(16) __half g_xh [BB*NN*DIN];    // x -> half, [m][k]
__device__ __align__(16) __half g_wq [DIN*DOUTC];    // W^T -> half, [n][k]
__device__ __align__(16) __half g_wk [DIN*DOUTC];
__device__ __align__(16) __half g_wv [DIN*DOUTC];
__device__ __align__(16) __half g_wo [DOUTC*DOUTC];
__device__ __align__(16) __half g_q  [BB*HH*NN*HD];  // [b,h,n,d], pre-scaled 1/8
__device__ __align__(16) __half g_k  [BB*HH*NN*HD];  // [b,h,n,d]
__device__ __align__(16) __half g_vt [BB*HH*HD*NN];  // [b,h,d,n]  (transposed V)
__device__ __align__(16) __half g_ctxh[BB*NN*DOUTC]; // [b,n,h*64+d]
__device__ int g_len[BB];

// ======================= helpers =======================
__device__ __forceinline__ void cp16(void* smem_dst, const void* gsrc) {
    uint32_t d = (uint32_t)__cvta_generic_to_shared(smem_dst);
    asm volatile("cp.async.cg.shared.global [%0], [%1], 16;" :: "r"(d), "l"(gsrc));
}
#define CP_COMMIT()  asm volatile("cp.async.commit_group;")
#define CP_WAIT(N)   asm volatile("cp.async.wait_group %0;" :: "n"(N))

// m16n8k16 fp16 MMA, fp32 accumulate. a: 4x .f16x2, b: 2x .f16x2.
__device__ __forceinline__ void mma_f16(float c[4], const uint32_t a[4],
                                        uint32_t b0, uint32_t b1) {
    asm volatile(
        "mma.sync.aligned.m16n8k16.row.col.f32.f16.f16.f32 "
        "{%0,%1,%2,%3},{%4,%5,%6,%7},{%8,%9},{%0,%1,%2,%3};"
        : "+f"(c[0]), "+f"(c[1]), "+f"(c[2]), "+f"(c[3])
        : "r"(a[0]), "r"(a[1]), "r"(a[2]), "r"(a[3]), "r"(b0), "r"(b1));
}

__device__ __forceinline__ uint32_t h2(float x, float y) {
    __half2 h = __floats2half2_rn(x, y);
    return *(uint32_t*)&h;
}

// ---------------------------------------------------------------------------
// x -> half
// ---------------------------------------------------------------------------
__global__ void round_xh(const float4* __restrict__ src) {
    uint32_t* dst = (uint32_t*)g_xh;
    const int n4 = BB * NN * DIN / 4;
    for (int i = blockIdx.x * blockDim.x + threadIdx.x; i < n4; i += gridDim.x * blockDim.x) {
        float4 v = src[i];
        dst[2 * i]     = h2(v.x, v.y);
        dst[2 * i + 1] = h2(v.z, v.w);
    }
}

// Transpose + convert weights: D[n][k] = half(W[k][n]). grid (32,32,4), block (32,8).
__global__ void prep_wh(const float* __restrict__ wq, const float* __restrict__ wk,
                        const float* __restrict__ wv, const float* __restrict__ wo) {
    __shared__ float tb[32][33];
    const int z = blockIdx.z;
    const float* W = (z == 0) ? wq : (z == 1) ? wk : (z == 2) ? wv : wo;
    __half* D = (z == 0) ? g_wq : (z == 1) ? g_wk : (z == 2) ? g_wv : g_wo;
    const int k0 = blockIdx.x * 32, n0 = blockIdx.y * 32;
    const int tx = threadIdx.x, ty = threadIdx.y;
    #pragma unroll
    for (int i = 0; i < 4; i++)
        tb[ty + i * 8][tx] = W[(size_t)(k0 + ty + i * 8) * DOUTC + n0 + tx];
    __syncthreads();
    #pragma unroll
    for (int i = 0; i < 4; i++)
        D[(size_t)(n0 + ty + i * 8) * DIN + k0 + tx] = __float2half_rn(tb[tx][ty + i * 8]);
}

// Per-batch valid length
__global__ void len_k(const int* __restrict__ am) {
    __shared__ int red[8];
    const int b = blockIdx.x;
    int s = 0;
    for (int i = threadIdx.x; i < NN; i += 256) s += am[b * NN + i];
    #pragma unroll
    for (int o = 16; o; o >>= 1) s += __shfl_xor_sync(0xffffffffu, s, o);
    if ((threadIdx.x & 31) == 0) red[threadIdx.x >> 5] = s;
    __syncthreads();
    if (threadIdx.x < 8) {
        int v = red[threadIdx.x];
        #pragma unroll
        for (int o = 4; o; o >>= 1) v += __shfl_xor_sync(0xffu, v, o);
        if (threadIdx.x == 0) g_len[b] = v;
    }
}

// ---------------------------------------------------------------------------
// FP16 GEMM: D[128,128] = A[128,K] @ Bt[128,K]^T via mma.m16n8k16.
// z=0/1/2: A=g_xh, B=g_w{q,k,v}; out head-major half (Q scaled 1/8, V transposed)
// z=3:     A=g_ctxh, B=g_wo; out = f32 + bias
// 8 warps = 2(m) x 4(n); warp tile 64x32; K chunk = 32 halves, double-buffered.
// Tile pitch 40 halves (20 words) -> conflict-free frag reads.
// ---------------------------------------------------------------------------
#define AP 40
#define HG_SMEM (2 * 2 * 128 * AP * 2)   // 40960 B

__global__ __launch_bounds__(256, 2) void h_gemm(float* __restrict__ outp,
                                                 const float* __restrict__ bias,
                                                 int zbase) {
    extern __shared__ __half hs[];
    __half* As = hs;                      // [2][128*AP]
    __half* Bs = hs + 2 * 128 * AP;

    const int tid = threadIdx.x, wid = tid >> 5, lane = tid & 31;
    const int g = lane >> 2, t = lane & 3;
    const int warp_m = wid >> 2, warp_n = wid & 3;
    const int m0 = blockIdx.x * 128, n0 = blockIdx.y * 128;
    const int z  = zbase + blockIdx.z;

    const __half* A = (z == 3) ? g_ctxh : g_xh;
    const __half* B = (z == 0) ? g_wq : (z == 1) ? g_wk : (z == 2) ? g_wv : g_wo;

    float acc[4][4][4];
    #pragma unroll
    for (int mi = 0; mi < 4; mi++)
        #pragma unroll
        for (int ni = 0; ni < 4; ni++) {
            acc[mi][ni][0] = 0.f; acc[mi][ni][1] = 0.f;
            acc[mi][ni][2] = 0.f; acc[mi][ni][3] = 0.f;
        }

    auto load_stage = [&](int s, int kc) {
        #pragma unroll
        for (int r = 0; r < 2; r++) {
            int idx = tid + 256 * r;          // 512 per tile
            int row = idx >> 2, c16 = idx & 3;
            cp16(&As[(s * 128 + row) * AP + c16 * 8],
                 A + (size_t)(m0 + row) * DIN + kc * 32 + c16 * 8);
            cp16(&Bs[(s * 128 + row) * AP + c16 * 8],
                 B + (size_t)(n0 + row) * DIN + kc * 32 + c16 * 8);
        }
        CP_COMMIT();
    };

    load_stage(0, 0);
    const int KT = DIN / 32;
    for (int kt = 0; kt < KT; kt++) {
        if (kt + 1 < KT) { load_stage((kt + 1) & 1, kt + 1); CP_WAIT(1); }
        else             { CP_WAIT(0); }
        __syncthreads();
        const __half* At = As + ((size_t)(kt & 1) * 128 + warp_m * 64) * AP;
        const __half* Bt = Bs + ((size_t)(kt & 1) * 128 + warp_n * 32) * AP;
        #pragma unroll
        for (int s2 = 0; s2 < 2; s2++) {      // two k16 steps per 32-chunk
            uint32_t bf[4][2];
            #pragma unroll
            for (int ni = 0; ni < 4; ni++) {
                bf[ni][0] = *(const uint32_t*)&Bt[(ni * 8 + g) * AP + s2 * 16 + 2 * t];
                bf[ni][1] = *(const uint32_t*)&Bt[(ni * 8 + g) * AP + s2 * 16 + 2 * t + 8];
            }
            #pragma unroll
            for (int mi = 0; mi < 4; mi++) {
                uint32_t af[4];
                af[0] = *(const uint32_t*)&At[(mi * 16 + g)     * AP + s2 * 16 + 2 * t];
                af[1] = *(const uint32_t*)&At[(mi * 16 + g + 8) * AP + s2 * 16 + 2 * t];
                af[2] = *(const uint32_t*)&At[(mi * 16 + g)     * AP + s2 * 16 + 2 * t + 8];
                af[3] = *(const uint32_t*)&At[(mi * 16 + g + 8) * AP + s2 * 16 + 2 * t + 8];
                #pragma unroll
                for (int ni = 0; ni < 4; ni++)
                    mma_f16(acc[mi][ni], af, bf[ni][0], bf[ni][1]);
            }
        }
        __syncthreads();
    }

    // Epilogue. C layout: c0,c1 = (row g, cols 2t,2t+1); c2,c3 = (row g+8).
    const int bi   = m0 / NN;
    const int tok0 = m0 % NN;
    #pragma unroll
    for (int mi = 0; mi < 4; mi++)
        #pragma unroll
        for (int ni = 0; ni < 4; ni++) {
            const float* c = acc[mi][ni];
            const int row = warp_m * 64 + mi * 16 + g;
            const int col = warp_n * 32 + ni * 8 + 2 * t;
            if (z < 3) {
                const int head = blockIdx.y * 2 + (col >> 6);
                const int hd   = col & 63;
                if (z == 2) {
                    // V transposed: g_vt[b,h,hd,token]
                    __half* vb = g_vt + ((size_t)(bi * HH + head) * HD + hd) * NN + tok0;
                    vb[row]          = __float2half_rn(c[0]);
                    vb[NN + row]     = __float2half_rn(c[1]);
                    vb[row + 8]      = __float2half_rn(c[2]);
                    vb[NN + row + 8] = __float2half_rn(c[3]);
                } else {
                    const float sc = (z == 0) ? 0.125f : 1.0f;  // fold 1/sqrt(64) into Q
                    __half* qb = (z == 0) ? g_q : g_k;
                    *(uint32_t*)(qb + ((size_t)(bi * HH + head) * NN + tok0 + row) * HD + hd)
                        = h2(c[0] * sc, c[1] * sc);
                    *(uint32_t*)(qb + ((size_t)(bi * HH + head) * NN + tok0 + row + 8) * HD + hd)
                        = h2(c[2] * sc, c[3] * sc);
                }
            } else {
                const float b0v = bias[n0 + col], b1v = bias[n0 + col + 1];
                *(float2*)(outp + (size_t)(m0 + row) * DOUTC + n0 + col)
                    = make_float2(c[0] + b0v, c[1] + b1v);
                *(float2*)(outp + (size_t)(m0 + row + 8) * DOUTC + n0 + col)
                    = make_float2(c[2] + b0v, c[3] + b1v);
            }
        }
}

// ---------------------------------------------------------------------------
// FP16 flash attention: mma.m16n8k16, register O/softmax, cp.async double-
// buffered K (row-major) + Vt (pre-transposed in gmem), padded-tile skip.
// Pitch 72 halves (36 words) -> conflict-free fragment reads.
// ---------------------------------------------------------------------------
#define KP 72
#define ATTN_SMEM ((2*64*KP + 2*64*KP + 8*16*KP) * 2 + 2 * 64 * 4)

__global__ __launch_bounds__(256, 2) void attn_h(const int* __restrict__ amask) {
    extern __shared__ __half hsm[];
    __half* sK  = hsm;                        // [2][64*KP]  [key][hd]
    __half* sVt = sK + 2 * 64 * KP;           // [2][64*KP]  [hd][key]
    __half* sP  = sVt + 2 * 64 * KP;          // [8][16*KP]
    int* sMask  = (int*)(sP + 8 * 16 * KP);   // [2][64]

    const int tid  = threadIdx.x;
    const int w    = tid >> 5;
    const int lane = tid & 31;
    const int g    = lane >> 2;
    const int t    = lane & 3;
    const int qt   = gridDim.x - 1 - blockIdx.x;   // heavy blocks first
    const int bh   = blockIdx.y;
    const int b    = bh >> 4;
    const int h    = bh & 15;
    const int q0   = qt * 128;
    const int qrow = q0 + w * 16;
    __half* sPw = sP + w * 16 * KP;

    const __half* kb  = g_k  + (size_t)bh * NN * HD;
    const __half* vtb = g_vt + (size_t)bh * HD * NN;
    const int len = g_len[b];

    // Q fragments (g_q pre-scaled by 1/8): 4 k16 groups x 4 half2 regs
    uint32_t qa[4][4];
    {
        const __half* q0p = g_q + ((size_t)bh * NN + qrow + g)     * HD;
        const __half* q1p = g_q + ((size_t)bh * NN + qrow + g + 8) * HD;
        #pragma unroll
        for (int kc = 0; kc < 4; kc++) {
            qa[kc][0] = *(const uint32_t*)&q0p[kc * 16 + 2 * t];
            qa[kc][1] = *(const uint32_t*)&q1p[kc * 16 + 2 * t];
            qa[kc][2] = *(const uint32_t*)&q0p[kc * 16 + 2 * t + 8];
            qa[kc][3] = *(const uint32_t*)&q1p[kc * 16 + 2 * t + 8];
        }
    }

    float o[8][4];
    #pragma unroll
    for (int nt = 0; nt < 8; nt++) { o[nt][0]=0.f; o[nt][1]=0.f; o[nt][2]=0.f; o[nt][3]=0.f; }
    float m0 = -INFINITY, m1 = -INFINITY, l0 = 0.f, l1 = 0.f;
    const int row0 = qrow + g, row1 = qrow + g + 8;

    auto load_tile = [&](int s, int kt) {
        #pragma unroll
        for (int r = 0; r < 2; r++) {
            int idx = tid + 256 * r;          // 512 per tile
            int row = idx >> 3, c16 = idx & 7;
            cp16(&sK [(s * 64 + row) * KP + c16 * 8],
                 kb + (size_t)(kt * 64 + row) * HD + c16 * 8);
            cp16(&sVt[(s * 64 + row) * KP + c16 * 8],
                 vtb + (size_t)row * NN + kt * 64 + c16 * 8);
        }
        if (tid < 16) cp16(&sMask[s * 64 + tid * 4], amask + b * NN + kt * 64 + tid * 4);
        CP_COMMIT();
    };

    const int kend    = min(q0 + 128, len);
    const int n_tiles = (kend + 63) >> 6;

    load_tile(0, 0);
    for (int kt = 0; kt < n_tiles; kt++) {
        if (kt + 1 < n_tiles) { load_tile((kt + 1) & 1, kt + 1); CP_WAIT(1); }
        else                  { CP_WAIT(0); }
        __syncthreads();
        const int s0 = kt & 1;
        const __half* K  = sK  + s0 * 64 * KP;
        const __half* Vt = sVt + s0 * 64 * KP;
        const int*    M  = sMask + s0 * 64;
        const int kk0 = kt * 64;

        // S = Qs K^T : B-frag = K[n][2t..] contiguous half2
        float s[8][4];
        #pragma unroll
        for (int nt = 0; nt < 8; nt++) { s[nt][0]=0.f; s[nt][1]=0.f; s[nt][2]=0.f; s[nt][3]=0.f; }
        #pragma unroll
        for (int kc = 0; kc < 4; kc++)
            #pragma unroll
            for (int nt = 0; nt < 8; nt++) {
                uint32_t b0 = *(const uint32_t*)&K[(nt * 8 + g) * KP + kc * 16 + 2 * t];
                uint32_t b1 = *(const uint32_t*)&K[(nt * 8 + g) * KP + kc * 16 + 2 * t + 8];
                mma_f16(s[nt], qa[kc], b0, b1);
            }

        // mask + register online softmax (Q already scaled)
        float mx0 = -1e30f, mx1 = -1e30f;
        #pragma unroll
        for (int nt = 0; nt < 8; nt++) {
            int j0 = nt * 8 + 2 * t, j1 = j0 + 1;
            bool mj0 = M[j0] != 0, mj1 = M[j1] != 0;
            s[nt][0] = (mj0 && (kk0 + j0 <= row0)) ? s[nt][0] : -1e30f;
            s[nt][1] = (mj1 && (kk0 + j1 <= row0)) ? s[nt][1] : -1e30f;
            s[nt][2] = (mj0 && (kk0 + j0 <= row1)) ? s[nt][2] : -1e30f;
            s[nt][3] = (mj1 && (kk0 + j1 <= row1)) ? s[nt][3] : -1e30f;
            mx0 = fmaxf(mx0, fmaxf(s[nt][0], s[nt][1]));
            mx1 = fmaxf(mx1, fmaxf(s[nt][2], s[nt][3]));
        }
        mx0 = fmaxf(mx0, __shfl_xor_sync(0xffffffffu, mx0, 1));
        mx0 = fmaxf(mx0, __shfl_xor_sync(0xffffffffu, mx0, 2));
        mx1 = fmaxf(mx1, __shfl_xor_sync(0xffffffffu, mx1, 1));
        mx1 = fmaxf(mx1, __shfl_xor_sync(0xffffffffu, mx1, 2));

        const float mn0 = fmaxf(m0, mx0), mn1 = fmaxf(m1, mx1);
        const float al0 = __expf(m0 - mn0), al1 = __expf(m1 - mn1);
        m0 = mn0; m1 = mn1;

        float sum0 = 0.f, sum1 = 0.f;
        #pragma unroll
        for (int nt = 0; nt < 8; nt++) {
            s[nt][0] = __expf(s[nt][0] - mn0);
            s[nt][1] = __expf(s[nt][1] - mn0);
            s[nt][2] = __expf(s[nt][2] - mn1);
            s[nt][3] = __expf(s[nt][3] - mn1);
            sum0 += s[nt][0] + s[nt][1];
            sum1 += s[nt][2] + s[nt][3];
        }
        sum0 += __shfl_xor_sync(0xffffffffu, sum0, 1);
        sum0 += __shfl_xor_sync(0xffffffffu, sum0, 2);
        sum1 += __shfl_xor_sync(0xffffffffu, sum1, 1);
        sum1 += __shfl_xor_sync(0xffffffffu, sum1, 2);
        l0 = l0 * al0 + sum0;
        l1 = l1 * al1 + sum1;

        // rescale O, stage P as half2 in warp-private smem
        #pragma unroll
        for (int nt = 0; nt < 8; nt++) {
            o[nt][0] *= al0; o[nt][1] *= al0; o[nt][2] *= al1; o[nt][3] *= al1;
            int j0 = nt * 8 + 2 * t;
            *(uint32_t*)&sPw[g * KP + j0]       = h2(s[nt][0], s[nt][1]);
            *(uint32_t*)&sPw[(g + 8) * KP + j0] = h2(s[nt][2], s[nt][3]);
        }
        __syncwarp();

        // O += P @ V : A from sPw [row][key], B from Vt [hd][key]
        #pragma unroll
        for (int kc = 0; kc < 4; kc++) {
            uint32_t av[4];
            av[0] = *(const uint32_t*)&sPw[g * KP + kc * 16 + 2 * t];
            av[1] = *(const uint32_t*)&sPw[(g + 8) * KP + kc * 16 + 2 * t];
            av[2] = *(const uint32_t*)&sPw[g * KP + kc * 16 + 2 * t + 8];
            av[3] = *(const uint32_t*)&sPw[(g + 8) * KP + kc * 16 + 2 * t + 8];
            #pragma unroll
            for (int nt = 0; nt < 8; nt++) {
                uint32_t b0 = *(const uint32_t*)&Vt[(nt * 8 + g) * KP + kc * 16 + 2 * t];
                uint32_t b1 = *(const uint32_t*)&Vt[(nt * 8 + g) * KP + kc * 16 + 2 * t + 8];
                mma_f16(o[nt], av, b0, b1);
            }
        }
        __syncthreads();
    }

    // normalize, convert to half, stage, coalesced f4 copy to ctx
    const float il0 = 1.0f / l0, il1 = 1.0f / l1;
    #pragma unroll
    for (int nt = 0; nt < 8; nt++) {
        int j0 = nt * 8 + 2 * t;
        *(uint32_t*)&sPw[g * KP + j0]       = h2(o[nt][0] * il0, o[nt][1] * il0);
        *(uint32_t*)&sPw[(g + 8) * KP + j0] = h2(o[nt][2] * il1, o[nt][3] * il1);
    }
    __syncwarp();
    __half* cb = g_ctxh + ((size_t)b * NN + qrow) * DOUTC + h * HD;
    #pragma unroll
    for (int r = 0; r < 4; r++) {
        int f4  = lane + 32 * r;              // 128 f4 = 16 rows x 8
        int row = f4 >> 3;
        int c16 = f4 & 7;
        *(float4*)(cb + (size_t)row * DOUTC + c16 * 8) =
            *(float4*)&sPw[row * KP + c16 * 8];
    }
}

// ---------------------------------------------------------------------------
extern "C" void kernel_launch(void* const* d_in, const int* in_sizes, int n_in,
                              void* d_out, int out_size) {
    const float* x  = (const float*)d_in[0];
    const int*   am = (const int*)  d_in[1];
    const float* Wq = (const float*)d_in[2];
    const float* Wk = (const float*)d_in[3];
    const float* Wv = (const float*)d_in[4];
    const float* Wo = (const float*)d_in[5];
    const float* bo = (const float*)d_in[6];
    float* out = (float*)d_out;

    cudaFuncSetAttribute(h_gemm, cudaFuncAttributeMaxDynamicSharedMemorySize, HG_SMEM);
    cudaFuncSetAttribute(attn_h, cudaFuncAttributeMaxDynamicSharedMemorySize, ATTN_SMEM);

    round_xh<<<512, 256>>>((const float4*)x);
    prep_wh<<<dim3(DIN / 32, DOUTC / 32, 4), dim3(32, 8)>>>(Wq, Wk, Wv, Wo);
    len_k<<<BB, 256>>>(am);

    h_gemm<<<dim3(BB * NN / 128, DOUTC / 128, 3), 256, HG_SMEM>>>(nullptr, nullptr, 0);
    attn_h<<<dim3(NN / 128, BB * HH), 256, ATTN_SMEM>>>(am);
    h_gemm<<<dim3(BB * NN / 128, DOUTC / 128, 1), 256, HG_SMEM>>>(out, bo, 3);
}

// round 16
// speedup vs baseline: 5.0798x; 1.0761x over previous
#include <cuda_runtime.h>
#include <cuda_fp16.h>
#include <math.h>
#include <stdint.h>

#define BB    4
#define NN    2048
#define DIN   1024
#define DOUTC 1024
#define HH    16
#define HD    64

// ---- scratch (__device__ globals; no allocs allowed) ----
__device__ __align__(16) __half g_xh [BB*NN*DIN];    // x -> half, [m][k]
__device__ __align__(16) __half g_wq [DIN*DOUTC];    // W^T -> half, [n][k]
__device__ __align__(16) __half g_wk [DIN*DOUTC];
__device__ __align__(16) __half g_wv [DIN*DOUTC];
__device__ __align__(16) __half g_wo [DOUTC*DOUTC];
__device__ __align__(16) __half g_q  [BB*HH*NN*HD];  // [b,h,n,d], pre-scaled 1/8
__device__ __align__(16) __half g_k  [BB*HH*NN*HD];  // [b,h,n,d]
__device__ __align__(16) __half g_vt [BB*HH*HD*NN];  // [b,h,d,n]  (transposed V)
__device__ __align__(16) __half g_ctxh[BB*NN*DOUTC]; // [b,n,h*64+d]
__device__ int g_len[BB];

// ======================= helpers =======================
__device__ __forceinline__ void cp16(void* smem_dst, const void* gsrc) {
    uint32_t d = (uint32_t)__cvta_generic_to_shared(smem_dst);
    asm volatile("cp.async.cg.shared.global [%0], [%1], 16;" :: "r"(d), "l"(gsrc));
}
#define CP_COMMIT()  asm volatile("cp.async.commit_group;")
#define CP_WAIT(N)   asm volatile("cp.async.wait_group %0;" :: "n"(N))

// m16n8k16 fp16 MMA, fp32 accumulate. a: 4x .f16x2, b: 2x .f16x2.
__device__ __forceinline__ void mma_f16(float c[4], const uint32_t a[4],
                                        uint32_t b0, uint32_t b1) {
    asm volatile(
        "mma.sync.aligned.m16n8k16.row.col.f32.f16.f16.f32 "
        "{%0,%1,%2,%3},{%4,%5,%6,%7},{%8,%9},{%0,%1,%2,%3};"
        : "+f"(c[0]), "+f"(c[1]), "+f"(c[2]), "+f"(c[3])
        : "r"(a[0]), "r"(a[1]), "r"(a[2]), "r"(a[3]), "r"(b0), "r"(b1));
}

__device__ __forceinline__ uint32_t h2(float x, float y) {
    __half2 h = __floats2half2_rn(x, y);
    return *(uint32_t*)&h;
}

// ---------------------------------------------------------------------------
// x -> half
// ---------------------------------------------------------------------------
__global__ void round_xh(const float4* __restrict__ src) {
    uint32_t* dst = (uint32_t*)g_xh;
    const int n4 = BB * NN * DIN / 4;
    for (int i = blockIdx.x * blockDim.x + threadIdx.x; i < n4; i += gridDim.x * blockDim.x) {
        float4 v = src[i];
        dst[2 * i]     = h2(v.x, v.y);
        dst[2 * i + 1] = h2(v.z, v.w);
    }
}

// Transpose + convert weights: D[n][k] = half(W[k][n]). grid (32,32,4), block (32,8).
__global__ void prep_wh(const float* __restrict__ wq, const float* __restrict__ wk,
                        const float* __restrict__ wv, const float* __restrict__ wo) {
    __shared__ float tb[32][33];
    const int z = blockIdx.z;
    const float* W = (z == 0) ? wq : (z == 1) ? wk : (z == 2) ? wv : wo;
    __half* D = (z == 0) ? g_wq : (z == 1) ? g_wk : (z == 2) ? g_wv : g_wo;
    const int k0 = blockIdx.x * 32, n0 = blockIdx.y * 32;
    const int tx = threadIdx.x, ty = threadIdx.y;
    #pragma unroll
    for (int i = 0; i < 4; i++)
        tb[ty + i * 8][tx] = W[(size_t)(k0 + ty + i * 8) * DOUTC + n0 + tx];
    __syncthreads();
    #pragma unroll
    for (int i = 0; i < 4; i++)
        D[(size_t)(n0 + ty + i * 8) * DIN + k0 + tx] = __float2half_rn(tb[tx][ty + i * 8]);
}

// Per-batch valid length
__global__ void len_k(const int* __restrict__ am) {
    __shared__ int red[8];
    const int b = blockIdx.x;
    int s = 0;
    for (int i = threadIdx.x; i < NN; i += 256) s += am[b * NN + i];
    #pragma unroll
    for (int o = 16; o; o >>= 1) s += __shfl_xor_sync(0xffffffffu, s, o);
    if ((threadIdx.x & 31) == 0) red[threadIdx.x >> 5] = s;
    __syncthreads();
    if (threadIdx.x < 8) {
        int v = red[threadIdx.x];
        #pragma unroll
        for (int o = 4; o; o >>= 1) v += __shfl_xor_sync(0xffu, v, o);
        if (threadIdx.x == 0) g_len[b] = v;
    }
}

// ---------------------------------------------------------------------------
// FP16 GEMM: D[128,128] = A[128,K] @ Bt[128,K]^T via mma.m16n8k16.
// K chunk = 64 halves (128B rows), double-buffered -> 16 iters, 64 MMAs/warp
// between barriers (was 32 iters x 32). Pitch 72 halves -> conflict-free.
// z=0/1/2: A=g_xh, B=g_w{q,k,v}; out head-major half (Q scaled 1/8, V transposed)
// z=3:     A=g_ctxh, B=g_wo; out = f32 + bias
// ---------------------------------------------------------------------------
#define AP 72
#define HG_SMEM (2 * 2 * 128 * AP * 2)   // 73728 B

__global__ __launch_bounds__(256, 2) void h_gemm(float* __restrict__ outp,
                                                 const float* __restrict__ bias,
                                                 int zbase) {
    extern __shared__ __half hs[];
    __half* As = hs;                      // [2][128*AP]
    __half* Bs = hs + 2 * 128 * AP;

    const int tid = threadIdx.x, wid = tid >> 5, lane = tid & 31;
    const int g = lane >> 2, t = lane & 3;
    const int warp_m = wid >> 2, warp_n = wid & 3;
    const int m0 = blockIdx.x * 128, n0 = blockIdx.y * 128;
    const int z  = zbase + blockIdx.z;

    const __half* A = (z == 3) ? g_ctxh : g_xh;
    const __half* B = (z == 0) ? g_wq : (z == 1) ? g_wk : (z == 2) ? g_wv : g_wo;

    float acc[4][4][4];
    #pragma unroll
    for (int mi = 0; mi < 4; mi++)
        #pragma unroll
        for (int ni = 0; ni < 4; ni++) {
            acc[mi][ni][0] = 0.f; acc[mi][ni][1] = 0.f;
            acc[mi][ni][2] = 0.f; acc[mi][ni][3] = 0.f;
        }

    auto load_stage = [&](int s, int kc) {
        #pragma unroll
        for (int r = 0; r < 4; r++) {
            int idx = tid + 256 * r;          // 1024 cp16 per tile
            int row = idx >> 3, c16 = idx & 7;
            cp16(&As[(s * 128 + row) * AP + c16 * 8],
                 A + (size_t)(m0 + row) * DIN + kc * 64 + c16 * 8);
            cp16(&Bs[(s * 128 + row) * AP + c16 * 8],
                 B + (size_t)(n0 + row) * DIN + kc * 64 + c16 * 8);
        }
        CP_COMMIT();
    };

    load_stage(0, 0);
    const int KT = DIN / 64;                  // 16 chunks
    for (int kt = 0; kt < KT; kt++) {
        if (kt + 1 < KT) { load_stage((kt + 1) & 1, kt + 1); CP_WAIT(1); }
        else             { CP_WAIT(0); }
        __syncthreads();
        const __half* At = As + ((size_t)(kt & 1) * 128 + warp_m * 64) * AP;
        const __half* Bt = Bs + ((size_t)(kt & 1) * 128 + warp_n * 32) * AP;
        #pragma unroll
        for (int s2 = 0; s2 < 4; s2++) {      // four k16 steps per 64-chunk
            uint32_t bf[4][2];
            #pragma unroll
            for (int ni = 0; ni < 4; ni++) {
                bf[ni][0] = *(const uint32_t*)&Bt[(ni * 8 + g) * AP + s2 * 16 + 2 * t];
                bf[ni][1] = *(const uint32_t*)&Bt[(ni * 8 + g) * AP + s2 * 16 + 2 * t + 8];
            }
            #pragma unroll
            for (int mi = 0; mi < 4; mi++) {
                uint32_t af[4];
                af[0] = *(const uint32_t*)&At[(mi * 16 + g)     * AP + s2 * 16 + 2 * t];
                af[1] = *(const uint32_t*)&At[(mi * 16 + g + 8) * AP + s2 * 16 + 2 * t];
                af[2] = *(const uint32_t*)&At[(mi * 16 + g)     * AP + s2 * 16 + 2 * t + 8];
                af[3] = *(const uint32_t*)&At[(mi * 16 + g + 8) * AP + s2 * 16 + 2 * t + 8];
                #pragma unroll
                for (int ni = 0; ni < 4; ni++)
                    mma_f16(acc[mi][ni], af, bf[ni][0], bf[ni][1]);
            }
        }
        __syncthreads();
    }

    // Epilogue. C layout: c0,c1 = (row g, cols 2t,2t+1); c2,c3 = (row g+8).
    const int bi   = m0 / NN;
    const int tok0 = m0 % NN;
    #pragma unroll
    for (int mi = 0; mi < 4; mi++)
        #pragma unroll
        for (int ni = 0; ni < 4; ni++) {
            const float* c = acc[mi][ni];
            const int row = warp_m * 64 + mi * 16 + g;
            const int col = warp_n * 32 + ni * 8 + 2 * t;
            if (z < 3) {
                const int head = blockIdx.y * 2 + (col >> 6);
                const int hd   = col & 63;
                if (z == 2) {
                    // V transposed: g_vt[b,h,hd,token]
                    __half* vb = g_vt + ((size_t)(bi * HH + head) * HD + hd) * NN + tok0;
                    vb[row]          = __float2half_rn(c[0]);
                    vb[NN + row]     = __float2half_rn(c[1]);
                    vb[row + 8]      = __float2half_rn(c[2]);
                    vb[NN + row + 8] = __float2half_rn(c[3]);
                } else {
                    const float sc = (z == 0) ? 0.125f : 1.0f;  // fold 1/sqrt(64) into Q
                    __half* qb = (z == 0) ? g_q : g_k;
                    *(uint32_t*)(qb + ((size_t)(bi * HH + head) * NN + tok0 + row) * HD + hd)
                        = h2(c[0] * sc, c[1] * sc);
                    *(uint32_t*)(qb + ((size_t)(bi * HH + head) * NN + tok0 + row + 8) * HD + hd)
                        = h2(c[2] * sc, c[3] * sc);
                }
            } else {
                const float b0v = bias[n0 + col], b1v = bias[n0 + col + 1];
                *(float2*)(outp + (size_t)(m0 + row) * DOUTC + n0 + col)
                    = make_float2(c[0] + b0v, c[1] + b1v);
                *(float2*)(outp + (size_t)(m0 + row + 8) * DOUTC + n0 + col)
                    = make_float2(c[2] + b0v, c[3] + b1v);
            }
        }
}

// ---------------------------------------------------------------------------
// FP16 flash attention: mma.m16n8k16, register O/softmax, cp.async double-
// buffered K (row-major) + Vt (pre-transposed in gmem), padded-tile skip.
// Pitch 72 halves (36 words) -> conflict-free fragment reads.
// ---------------------------------------------------------------------------
#define KP 72
#define ATTN_SMEM ((2*64*KP + 2*64*KP + 8*16*KP) * 2 + 2 * 64 * 4)

__global__ __launch_bounds__(256, 2) void attn_h(const int* __restrict__ amask) {
    extern __shared__ __half hsm[];
    __half* sK  = hsm;                        // [2][64*KP]  [key][hd]
    __half* sVt = sK + 2 * 64 * KP;           // [2][64*KP]  [hd][key]
    __half* sP  = sVt + 2 * 64 * KP;          // [8][16*KP]
    int* sMask  = (int*)(sP + 8 * 16 * KP);   // [2][64]

    const int tid  = threadIdx.x;
    const int w    = tid >> 5;
    const int lane = tid & 31;
    const int g    = lane >> 2;
    const int t    = lane & 3;
    const int qt   = gridDim.x - 1 - blockIdx.x;   // heavy blocks first
    const int bh   = blockIdx.y;
    const int b    = bh >> 4;
    const int h    = bh & 15;
    const int q0   = qt * 128;
    const int qrow = q0 + w * 16;
    __half* sPw = sP + w * 16 * KP;

    const __half* kb  = g_k  + (size_t)bh * NN * HD;
    const __half* vtb = g_vt + (size_t)bh * HD * NN;
    const int len = g_len[b];

    // Q fragments (g_q pre-scaled by 1/8): 4 k16 groups x 4 half2 regs
    uint32_t qa[4][4];
    {
        const __half* q0p = g_q + ((size_t)bh * NN + qrow + g)     * HD;
        const __half* q1p = g_q + ((size_t)bh * NN + qrow + g + 8) * HD;
        #pragma unroll
        for (int kc = 0; kc < 4; kc++) {
            qa[kc][0] = *(const uint32_t*)&q0p[kc * 16 + 2 * t];
            qa[kc][1] = *(const uint32_t*)&q1p[kc * 16 + 2 * t];
            qa[kc][2] = *(const uint32_t*)&q0p[kc * 16 + 2 * t + 8];
            qa[kc][3] = *(const uint32_t*)&q1p[kc * 16 + 2 * t + 8];
        }
    }

    float o[8][4];
    #pragma unroll
    for (int nt = 0; nt < 8; nt++) { o[nt][0]=0.f; o[nt][1]=0.f; o[nt][2]=0.f; o[nt][3]=0.f; }
    float m0 = -INFINITY, m1 = -INFINITY, l0 = 0.f, l1 = 0.f;
    const int row0 = qrow + g, row1 = qrow + g + 8;

    auto load_tile = [&](int s, int kt) {
        #pragma unroll
        for (int r = 0; r < 2; r++) {
            int idx = tid + 256 * r;          // 512 per tile
            int row = idx >> 3, c16 = idx & 7;
            cp16(&sK [(s * 64 + row) * KP + c16 * 8],
                 kb + (size_t)(kt * 64 + row) * HD + c16 * 8);
            cp16(&sVt[(s * 64 + row) * KP + c16 * 8],
                 vtb + (size_t)row * NN + kt * 64 + c16 * 8);
        }
        if (tid < 16) cp16(&sMask[s * 64 + tid * 4], amask + b * NN + kt * 64 + tid * 4);
        CP_COMMIT();
    };

    const int kend    = min(q0 + 128, len);
    const int n_tiles = (kend + 63) >> 6;

    load_tile(0, 0);
    for (int kt = 0; kt < n_tiles; kt++) {
        if (kt + 1 < n_tiles) { load_tile((kt + 1) & 1, kt + 1); CP_WAIT(1); }
        else                  { CP_WAIT(0); }
        __syncthreads();
        const int s0 = kt & 1;
        const __half* K  = sK  + s0 * 64 * KP;
        const __half* Vt = sVt + s0 * 64 * KP;
        const int*    M  = sMask + s0 * 64;
        const int kk0 = kt * 64;

        // S = Qs K^T : B-frag = K[n][2t..] contiguous half2
        float s[8][4];
        #pragma unroll
        for (int nt = 0; nt < 8; nt++) { s[nt][0]=0.f; s[nt][1]=0.f; s[nt][2]=0.f; s[nt][3]=0.f; }
        #pragma unroll
        for (int kc = 0; kc < 4; kc++)
            #pragma unroll
            for (int nt = 0; nt < 8; nt++) {
                uint32_t b0 = *(const uint32_t*)&K[(nt * 8 + g) * KP + kc * 16 + 2 * t];
                uint32_t b1 = *(const uint32_t*)&K[(nt * 8 + g) * KP + kc * 16 + 2 * t + 8];
                mma_f16(s[nt], qa[kc], b0, b1);
            }

        // mask + register online softmax (Q already scaled)
        float mx0 = -1e30f, mx1 = -1e30f;
        #pragma unroll
        for (int nt = 0; nt < 8; nt++) {
            int j0 = nt * 8 + 2 * t, j1 = j0 + 1;
            bool mj0 = M[j0] != 0, mj1 = M[j1] != 0;
            s[nt][0] = (mj0 && (kk0 + j0 <= row0)) ? s[nt][0] : -1e30f;
            s[nt][1] = (mj1 && (kk0 + j1 <= row0)) ? s[nt][1] : -1e30f;
            s[nt][2] = (mj0 && (kk0 + j0 <= row1)) ? s[nt][2] : -1e30f;
            s[nt][3] = (mj1 && (kk0 + j1 <= row1)) ? s[nt][3] : -1e30f;
            mx0 = fmaxf(mx0, fmaxf(s[nt][0], s[nt][1]));
            mx1 = fmaxf(mx1, fmaxf(s[nt][2], s[nt][3]));
        }
        mx0 = fmaxf(mx0, __shfl_xor_sync(0xffffffffu, mx0, 1));
        mx0 = fmaxf(mx0, __shfl_xor_sync(0xffffffffu, mx0, 2));
        mx1 = fmaxf(mx1, __shfl_xor_sync(0xffffffffu, mx1, 1));
        mx1 = fmaxf(mx1, __shfl_xor_sync(0xffffffffu, mx1, 2));

        const float mn0 = fmaxf(m0, mx0), mn1 = fmaxf(m1, mx1);
        const float al0 = __expf(m0 - mn0), al1 = __expf(m1 - mn1);
        m0 = mn0; m1 = mn1;

        float sum0 = 0.f, sum1 = 0.f;
        #pragma unroll
        for (int nt = 0; nt < 8; nt++) {
            s[nt][0] = __expf(s[nt][0] - mn0);
            s[nt][1] = __expf(s[nt][1] - mn0);
            s[nt][2] = __expf(s[nt][2] - mn1);
            s[nt][3] = __expf(s[nt][3] - mn1);
            sum0 += s[nt][0] + s[nt][1];
            sum1 += s[nt][2] + s[nt][3];
        }
        sum0 += __shfl_xor_sync(0xffffffffu, sum0, 1);
        sum0 += __shfl_xor_sync(0xffffffffu, sum0, 2);
        sum1 += __shfl_xor_sync(0xffffffffu, sum1, 1);
        sum1 += __shfl_xor_sync(0xffffffffu, sum1, 2);
        l0 = l0 * al0 + sum0;
        l1 = l1 * al1 + sum1;

        // rescale O, stage P as half2 in warp-private smem
        #pragma unroll
        for (int nt = 0; nt < 8; nt++) {
            o[nt][0] *= al0; o[nt][1] *= al0; o[nt][2] *= al1; o[nt][3] *= al1;
            int j0 = nt * 8 + 2 * t;
            *(uint32_t*)&sPw[g * KP + j0]       = h2(s[nt][0], s[nt][1]);
            *(uint32_t*)&sPw[(g + 8) * KP + j0] = h2(s[nt][2], s[nt][3]);
        }
        __syncwarp();

        // O += P @ V : A from sPw [row][key], B from Vt [hd][key]
        #pragma unroll
        for (int kc = 0; kc < 4; kc++) {
            uint32_t av[4];
            av[0] = *(const uint32_t*)&sPw[g * KP + kc * 16 + 2 * t];
            av[1] = *(const uint32_t*)&sPw[(g + 8) * KP + kc * 16 + 2 * t];
            av[2] = *(const uint32_t*)&sPw[g * KP + kc * 16 + 2 * t + 8];
            av[3] = *(const uint32_t*)&sPw[(g + 8) * KP + kc * 16 + 2 * t + 8];
            #pragma unroll
            for (int nt = 0; nt < 8; nt++) {
                uint32_t b0 = *(const uint32_t*)&Vt[(nt * 8 + g) * KP + kc * 16 + 2 * t];
                uint32_t b1 = *(const uint32_t*)&Vt[(nt * 8 + g) * KP + kc * 16 + 2 * t + 8];
                mma_f16(o[nt], av, b0, b1);
            }
        }
        __syncthreads();
    }

    // normalize, convert to half, stage, coalesced f4 copy to ctx
    const float il0 = 1.0f / l0, il1 = 1.0f / l1;
    #pragma unroll
    for (int nt = 0; nt < 8; nt++) {
        int j0 = nt * 8 + 2 * t;
        *(uint32_t*)&sPw[g * KP + j0]       = h2(o[nt][0] * il0, o[nt][1] * il0);
        *(uint32_t*)&sPw[(g + 8) * KP + j0] = h2(o[nt][2] * il1, o[nt][3] * il1);
    }
    __syncwarp();
    __half* cb = g_ctxh + ((size_t)b * NN + qrow) * DOUTC + h * HD;
    #pragma unroll
    for (int r = 0; r < 4; r++) {
        int f4  = lane + 32 * r;              // 128 f4 = 16 rows x 8
        int row = f4 >> 3;
        int c16 = f4 & 7;
        *(float4*)(cb + (size_t)row * DOUTC + c16 * 8) =
            *(float4*)&sPw[row * KP + c16 * 8];
    }
}

// ---------------------------------------------------------------------------
extern "C" void kernel_launch(void* const* d_in, const int* in_sizes, int n_in,
                              void* d_out, int out_size) {
    const float* x  = (const float*)d_in[0];
    const int*   am = (const int*)  d_in[1];
    const float* Wq = (const float*)d_in[2];
    const float* Wk = (const float*)d_in[3];
    const float* Wv = (const float*)d_in[4];
    const float* Wo = (const float*)d_in[5];
    const float* bo = (const float*)d_in[6];
    float* out = (float*)d_out;

    cudaFuncSetAttribute(h_gemm, cudaFuncAttributeMaxDynamicSharedMemorySize, HG_SMEM);
    cudaFuncSetAttribute(attn_h, cudaFuncAttributeMaxDynamicSharedMemorySize, ATTN_SMEM);

    round_xh<<<512, 256>>>((const float4*)x);
    prep_wh<<<dim3(DIN / 32, DOUTC / 32, 4), dim3(32, 8)>>>(Wq, Wk, Wv, Wo);
    len_k<<<BB, 256>>>(am);

    h_gemm<<<dim3(BB * NN / 128, DOUTC / 128, 3), 256, HG_SMEM>>>(nullptr, nullptr, 0);
    attn_h<<<dim3(NN / 128, BB * HH), 256, ATTN_SMEM>>>(am);
    h_gemm<<<dim3(BB * NN / 128, DOUTC / 128, 1), 256, HG_SMEM>>>(out, bo, 3);
}

// round 17
// speedup vs baseline: 5.3057x; 1.0445x over previous
#include <cuda_runtime.h>
#include <cuda_fp16.h>
#include <math.h>
#include <stdint.h>

#define BB    4
#define NN    2048
#define DIN   1024
#define DOUTC 1024
#define HH    16
#define HD    64

// ---- scratch (__device__ globals; no allocs allowed) ----
__device__ __align__(16) __half g_xh [BB*NN*DIN];    // x -> half, [m][k]
__device__ __align__(16) __half g_wq [DIN*DOUTC];    // W^T -> half, [n][k]
__device__ __align__(16) __half g_wk [DIN*DOUTC];
__device__ __align__(16) __half g_wv [DIN*DOUTC];
__device__ __align__(16) __half g_wo [DOUTC*DOUTC];
__device__ __align__(16) __half g_q  [BB*HH*NN*HD];  // [b,h,n,d], pre-scaled 1/8
__device__ __align__(16) __half g_k  [BB*HH*NN*HD];  // [b,h,n,d]
__device__ __align__(16) __half g_vt [BB*HH*HD*NN];  // [b,h,d,n]  (transposed V)
__device__ __align__(16) __half g_ctxh[BB*NN*DOUTC]; // [b,n,h*64+d]
__device__ int g_len[BB];

// ======================= helpers =======================
__device__ __forceinline__ void cp16(void* smem_dst, const void* gsrc) {
    uint32_t d = (uint32_t)__cvta_generic_to_shared(smem_dst);
    asm volatile("cp.async.cg.shared.global [%0], [%1], 16;" :: "r"(d), "l"(gsrc));
}
#define CP_COMMIT()  asm volatile("cp.async.commit_group;")
#define CP_WAIT(N)   asm volatile("cp.async.wait_group %0;" :: "n"(N))

// m16n8k16 fp16 MMA, fp32 accumulate. a: 4x .f16x2, b: 2x .f16x2.
__device__ __forceinline__ void mma_f16(float c[4], const uint32_t a[4],
                                        uint32_t b0, uint32_t b1) {
    asm volatile(
        "mma.sync.aligned.m16n8k16.row.col.f32.f16.f16.f32 "
        "{%0,%1,%2,%3},{%4,%5,%6,%7},{%8,%9},{%0,%1,%2,%3};"
        : "+f"(c[0]), "+f"(c[1]), "+f"(c[2]), "+f"(c[3])
        : "r"(a[0]), "r"(a[1]), "r"(a[2]), "r"(a[3]), "r"(b0), "r"(b1));
}

// warp-collective ldmatrix x4 (4 x m8n8 b16 tiles)
__device__ __forceinline__ void ldsm4(uint32_t r[4], uint32_t saddr) {
    asm volatile("ldmatrix.sync.aligned.m8n8.x4.shared.b16 {%0,%1,%2,%3}, [%4];"
        : "=r"(r[0]), "=r"(r[1]), "=r"(r[2]), "=r"(r[3]) : "r"(saddr));
}

__device__ __forceinline__ uint32_t h2(float x, float y) {
    __half2 h = __floats2half2_rn(x, y);
    return *(uint32_t*)&h;
}

// ---------------------------------------------------------------------------
// x -> half
// ---------------------------------------------------------------------------
__global__ void round_xh(const float4* __restrict__ src) {
    uint32_t* dst = (uint32_t*)g_xh;
    const int n4 = BB * NN * DIN / 4;
    for (int i = blockIdx.x * blockDim.x + threadIdx.x; i < n4; i += gridDim.x * blockDim.x) {
        float4 v = src[i];
        dst[2 * i]     = h2(v.x, v.y);
        dst[2 * i + 1] = h2(v.z, v.w);
    }
}

// Transpose + convert weights: D[n][k] = half(W[k][n]). grid (32,32,4), block (32,8).
__global__ void prep_wh(const float* __restrict__ wq, const float* __restrict__ wk,
                        const float* __restrict__ wv, const float* __restrict__ wo) {
    __shared__ float tb[32][33];
    const int z = blockIdx.z;
    const float* W = (z == 0) ? wq : (z == 1) ? wk : (z == 2) ? wv : wo;
    __half* D = (z == 0) ? g_wq : (z == 1) ? g_wk : (z == 2) ? g_wv : g_wo;
    const int k0 = blockIdx.x * 32, n0 = blockIdx.y * 32;
    const int tx = threadIdx.x, ty = threadIdx.y;
    #pragma unroll
    for (int i = 0; i < 4; i++)
        tb[ty + i * 8][tx] = W[(size_t)(k0 + ty + i * 8) * DOUTC + n0 + tx];
    __syncthreads();
    #pragma unroll
    for (int i = 0; i < 4; i++)
        D[(size_t)(n0 + ty + i * 8) * DIN + k0 + tx] = __float2half_rn(tb[tx][ty + i * 8]);
}

// Per-batch valid length
__global__ void len_k(const int* __restrict__ am) {
    __shared__ int red[8];
    const int b = blockIdx.x;
    int s = 0;
    for (int i = threadIdx.x; i < NN; i += 256) s += am[b * NN + i];
    #pragma unroll
    for (int o = 16; o; o >>= 1) s += __shfl_xor_sync(0xffffffffu, s, o);
    if ((threadIdx.x & 31) == 0) red[threadIdx.x >> 5] = s;
    __syncthreads();
    if (threadIdx.x < 8) {
        int v = red[threadIdx.x];
        #pragma unroll
        for (int o = 4; o; o >>= 1) v += __shfl_xor_sync(0xffu, v, o);
        if (threadIdx.x == 0) g_len[b] = v;
    }
}

// ---------------------------------------------------------------------------
// FP16 GEMM: D[128,128] = A[128,K] @ Bt[128,K]^T via mma.m16n8k16.
// K chunk = 64 halves, double-buffered; fragment loads via ldmatrix.x4
// (6 LSU instr / 16 MMA, was 24). Pitch 72 halves -> conflict-free phases.
// z=0/1/2: A=g_xh, B=g_w{q,k,v}; out head-major half (Q scaled 1/8, V transposed)
// z=3:     A=g_ctxh, B=g_wo; out = f32 + bias
// ---------------------------------------------------------------------------
#define AP 72
#define HG_SMEM (2 * 2 * 128 * AP * 2)   // 73728 B

__global__ __launch_bounds__(256, 2) void h_gemm(float* __restrict__ outp,
                                                 const float* __restrict__ bias,
                                                 int zbase) {
    extern __shared__ __half hs[];
    __half* As = hs;                      // [2][128*AP]
    __half* Bs = hs + 2 * 128 * AP;

    const int tid = threadIdx.x, wid = tid >> 5, lane = tid & 31;
    const int g = lane >> 2, t = lane & 3;
    const int warp_m = wid >> 2, warp_n = wid & 3;
    const int m0 = blockIdx.x * 128, n0 = blockIdx.y * 128;
    const int z  = zbase + blockIdx.z;

    const __half* A = (z == 3) ? g_ctxh : g_xh;
    const __half* B = (z == 0) ? g_wq : (z == 1) ? g_wk : (z == 2) ? g_wv : g_wo;

    // ldmatrix per-lane source offsets (halves):
    // A x4 covers one 16x16 tile: matrices (g,2t),(g+8,2t),(g,2t+8),(g+8,2t+8)
    const int a_row = ((lane >> 3) & 1) * 8 + (lane & 7);
    const int a_col = (lane >> 4) * 8;
    // B x4 covers two n8 tiles x k16: regs = {b0(ni),b1(ni),b0(ni+1),b1(ni+1)}
    const int b_row = (lane >> 4) * 8 + (lane & 7);
    const int b_col = ((lane >> 3) & 1) * 8;
    const uint32_t sA = (uint32_t)__cvta_generic_to_shared(As);
    const uint32_t sB = (uint32_t)__cvta_generic_to_shared(Bs);

    float acc[4][4][4];
    #pragma unroll
    for (int mi = 0; mi < 4; mi++)
        #pragma unroll
        for (int ni = 0; ni < 4; ni++) {
            acc[mi][ni][0] = 0.f; acc[mi][ni][1] = 0.f;
            acc[mi][ni][2] = 0.f; acc[mi][ni][3] = 0.f;
        }

    auto load_stage = [&](int s, int kc) {
        #pragma unroll
        for (int r = 0; r < 4; r++) {
            int idx = tid + 256 * r;          // 1024 cp16 per stage
            int row = idx >> 3, c16 = idx & 7;
            cp16(&As[(s * 128 + row) * AP + c16 * 8],
                 A + (size_t)(m0 + row) * DIN + kc * 64 + c16 * 8);
            cp16(&Bs[(s * 128 + row) * AP + c16 * 8],
                 B + (size_t)(n0 + row) * DIN + kc * 64 + c16 * 8);
        }
        CP_COMMIT();
    };

    load_stage(0, 0);
    const int KT = DIN / 64;                  // 16 chunks
    for (int kt = 0; kt < KT; kt++) {
        if (kt + 1 < KT) { load_stage((kt + 1) & 1, kt + 1); CP_WAIT(1); }
        else             { CP_WAIT(0); }
        __syncthreads();
        const int st = kt & 1;
        const uint32_t aBase = sA + ((st * 128 + warp_m * 64 + a_row) * AP + a_col) * 2;
        const uint32_t bBase = sB + ((st * 128 + warp_n * 32 + b_row) * AP + b_col) * 2;
        #pragma unroll
        for (int s2 = 0; s2 < 4; s2++) {      // four k16 steps per 64-chunk
            uint32_t bm0[4], bm1[4];
            ldsm4(bm0, bBase + (s2 * 16) * 2);               // ni 0,1
            ldsm4(bm1, bBase + (16 * AP + s2 * 16) * 2);     // ni 2,3
            #pragma unroll
            for (int mi = 0; mi < 4; mi++) {
                uint32_t af[4];
                ldsm4(af, aBase + (mi * 16 * AP + s2 * 16) * 2);
                mma_f16(acc[mi][0], af, bm0[0], bm0[1]);
                mma_f16(acc[mi][1], af, bm0[2], bm0[3]);
                mma_f16(acc[mi][2], af, bm1[0], bm1[1]);
                mma_f16(acc[mi][3], af, bm1[2], bm1[3]);
            }
        }
        __syncthreads();
    }

    // Epilogue. C layout: c0,c1 = (row g, cols 2t,2t+1); c2,c3 = (row g+8).
    const int bi   = m0 / NN;
    const int tok0 = m0 % NN;
    #pragma unroll
    for (int mi = 0; mi < 4; mi++)
        #pragma unroll
        for (int ni = 0; ni < 4; ni++) {
            const float* c = acc[mi][ni];
            const int row = warp_m * 64 + mi * 16 + g;
            const int col = warp_n * 32 + ni * 8 + 2 * t;
            if (z < 3) {
                const int head = blockIdx.y * 2 + (col >> 6);
                const int hd   = col & 63;
                if (z == 2) {
                    // V transposed: g_vt[b,h,hd,token]
                    __half* vb = g_vt + ((size_t)(bi * HH + head) * HD + hd) * NN + tok0;
                    vb[row]          = __float2half_rn(c[0]);
                    vb[NN + row]     = __float2half_rn(c[1]);
                    vb[row + 8]      = __float2half_rn(c[2]);
                    vb[NN + row + 8] = __float2half_rn(c[3]);
                } else {
                    const float sc = (z == 0) ? 0.125f : 1.0f;  // fold 1/sqrt(64) into Q
                    __half* qb = (z == 0) ? g_q : g_k;
                    *(uint32_t*)(qb + ((size_t)(bi * HH + head) * NN + tok0 + row) * HD + hd)
                        = h2(c[0] * sc, c[1] * sc);
                    *(uint32_t*)(qb + ((size_t)(bi * HH + head) * NN + tok0 + row + 8) * HD + hd)
                        = h2(c[2] * sc, c[3] * sc);
                }
            } else {
                const float b0v = bias[n0 + col], b1v = bias[n0 + col + 1];
                *(float2*)(outp + (size_t)(m0 + row) * DOUTC + n0 + col)
                    = make_float2(c[0] + b0v, c[1] + b1v);
                *(float2*)(outp + (size_t)(m0 + row + 8) * DOUTC + n0 + col)
                    = make_float2(c[2] + b0v, c[3] + b1v);
            }
        }
}

// ---------------------------------------------------------------------------
// FP16 flash attention: mma.m16n8k16, register O/softmax, cp.async double-
// buffered K (row-major) + Vt (pre-transposed in gmem), padded-tile skip.
// Pitch 72 halves (36 words) -> conflict-free fragment reads.
// ---------------------------------------------------------------------------
#define KP 72
#define ATTN_SMEM ((2*64*KP + 2*64*KP + 8*16*KP) * 2 + 2 * 64 * 4)

__global__ __launch_bounds__(256, 2) void attn_h(const int* __restrict__ amask) {
    extern __shared__ __half hsm[];
    __half* sK  = hsm;                        // [2][64*KP]  [key][hd]
    __half* sVt = sK + 2 * 64 * KP;           // [2][64*KP]  [hd][key]
    __half* sP  = sVt + 2 * 64 * KP;          // [8][16*KP]
    int* sMask  = (int*)(sP + 8 * 16 * KP);   // [2][64]

    const int tid  = threadIdx.x;
    const int w    = tid >> 5;
    const int lane = tid & 31;
    const int g    = lane >> 2;
    const int t    = lane & 3;
    const int qt   = gridDim.x - 1 - blockIdx.x;   // heavy blocks first
    const int bh   = blockIdx.y;
    const int b    = bh >> 4;
    const int h    = bh & 15;
    const int q0   = qt * 128;
    const int qrow = q0 + w * 16;
    __half* sPw = sP + w * 16 * KP;

    const __half* kb  = g_k  + (size_t)bh * NN * HD;
    const __half* vtb = g_vt + (size_t)bh * HD * NN;
    const int len = g_len[b];

    // Q fragments (g_q pre-scaled by 1/8): 4 k16 groups x 4 half2 regs
    uint32_t qa[4][4];
    {
        const __half* q0p = g_q + ((size_t)bh * NN + qrow + g)     * HD;
        const __half* q1p = g_q + ((size_t)bh * NN + qrow + g + 8) * HD;
        #pragma unroll
        for (int kc = 0; kc < 4; kc++) {
            qa[kc][0] = *(const uint32_t*)&q0p[kc * 16 + 2 * t];
            qa[kc][1] = *(const uint32_t*)&q1p[kc * 16 + 2 * t];
            qa[kc][2] = *(const uint32_t*)&q0p[kc * 16 + 2 * t + 8];
            qa[kc][3] = *(const uint32_t*)&q1p[kc * 16 + 2 * t + 8];
        }
    }

    float o[8][4];
    #pragma unroll
    for (int nt = 0; nt < 8; nt++) { o[nt][0]=0.f; o[nt][1]=0.f; o[nt][2]=0.f; o[nt][3]=0.f; }
    float m0 = -INFINITY, m1 = -INFINITY, l0 = 0.f, l1 = 0.f;
    const int row0 = qrow + g, row1 = qrow + g + 8;

    auto load_tile = [&](int s, int kt) {
        #pragma unroll
        for (int r = 0; r < 2; r++) {
            int idx = tid + 256 * r;          // 512 per tile
            int row = idx >> 3, c16 = idx & 7;
            cp16(&sK [(s * 64 + row) * KP + c16 * 8],
                 kb + (size_t)(kt * 64 + row) * HD + c16 * 8);
            cp16(&sVt[(s * 64 + row) * KP + c16 * 8],
                 vtb + (size_t)row * NN + kt * 64 + c16 * 8);
        }
        if (tid < 16) cp16(&sMask[s * 64 + tid * 4], amask + b * NN + kt * 64 + tid * 4);
        CP_COMMIT();
    };

    const int kend    = min(q0 + 128, len);
    const int n_tiles = (kend + 63) >> 6;

    load_tile(0, 0);
    for (int kt = 0; kt < n_tiles; kt++) {
        if (kt + 1 < n_tiles) { load_tile((kt + 1) & 1, kt + 1); CP_WAIT(1); }
        else                  { CP_WAIT(0); }
        __syncthreads();
        const int s0 = kt & 1;
        const __half* K  = sK  + s0 * 64 * KP;
        const __half* Vt = sVt + s0 * 64 * KP;
        const int*    M  = sMask + s0 * 64;
        const int kk0 = kt * 64;

        // S = Qs K^T : B-frag = K[n][2t..] contiguous half2
        float s[8][4];
        #pragma unroll
        for (int nt = 0; nt < 8; nt++) { s[nt][0]=0.f; s[nt][1]=0.f; s[nt][2]=0.f; s[nt][3]=0.f; }
        #pragma unroll
        for (int kc = 0; kc < 4; kc++)
            #pragma unroll
            for (int nt = 0; nt < 8; nt++) {
                uint32_t b0 = *(const uint32_t*)&K[(nt * 8 + g) * KP + kc * 16 + 2 * t];
                uint32_t b1 = *(const uint32_t*)&K[(nt * 8 + g) * KP + kc * 16 + 2 * t + 8];
                mma_f16(s[nt], qa[kc], b0, b1);
            }

        // mask + register online softmax (Q already scaled)
        float mx0 = -1e30f, mx1 = -1e30f;
        #pragma unroll
        for (int nt = 0; nt < 8; nt++) {
            int j0 = nt * 8 + 2 * t, j1 = j0 + 1;
            bool mj0 = M[j0] != 0, mj1 = M[j1] != 0;
            s[nt][0] = (mj0 && (kk0 + j0 <= row0)) ? s[nt][0] : -1e30f;
            s[nt][1] = (mj1 && (kk0 + j1 <= row0)) ? s[nt][1] : -1e30f;
            s[nt][2] = (mj0 && (kk0 + j0 <= row1)) ? s[nt][2] : -1e30f;
            s[nt][3] = (mj1 && (kk0 + j1 <= row1)) ? s[nt][3] : -1e30f;
            mx0 = fmaxf(mx0, fmaxf(s[nt][0], s[nt][1]));
            mx1 = fmaxf(mx1, fmaxf(s[nt][2], s[nt][3]));
        }
        mx0 = fmaxf(mx0, __shfl_xor_sync(0xffffffffu, mx0, 1));
        mx0 = fmaxf(mx0, __shfl_xor_sync(0xffffffffu, mx0, 2));
        mx1 = fmaxf(mx1, __shfl_xor_sync(0xffffffffu, mx1, 1));
        mx1 = fmaxf(mx1, __shfl_xor_sync(0xffffffffu, mx1, 2));

        const float mn0 = fmaxf(m0, mx0), mn1 = fmaxf(m1, mx1);
        const float al0 = __expf(m0 - mn0), al1 = __expf(m1 - mn1);
        m0 = mn0; m1 = mn1;

        float sum0 = 0.f, sum1 = 0.f;
        #pragma unroll
        for (int nt = 0; nt < 8; nt++) {
            s[nt][0] = __expf(s[nt][0] - mn0);
            s[nt][1] = __expf(s[nt][1] - mn0);
            s[nt][2] = __expf(s[nt][2] - mn1);
            s[nt][3] = __expf(s[nt][3] - mn1);
            sum0 += s[nt][0] + s[nt][1];
            sum1 += s[nt][2] + s[nt][3];
        }
        sum0 += __shfl_xor_sync(0xffffffffu, sum0, 1);
        sum0 += __shfl_xor_sync(0xffffffffu, sum0, 2);
        sum1 += __shfl_xor_sync(0xffffffffu, sum1, 1);
        sum1 += __shfl_xor_sync(0xffffffffu, sum1, 2);
        l0 = l0 * al0 + sum0;
        l1 = l1 * al1 + sum1;

        // rescale O, stage P as half2 in warp-private smem
        #pragma unroll
        for (int nt = 0; nt < 8; nt++) {
            o[nt][0] *= al0; o[nt][1] *= al0; o[nt][2] *= al1; o[nt][3] *= al1;
            int j0 = nt * 8 + 2 * t;
            *(uint32_t*)&sPw[g * KP + j0]       = h2(s[nt][0], s[nt][1]);
            *(uint32_t*)&sPw[(g + 8) * KP + j0] = h2(s[nt][2], s[nt][3]);
        }
        __syncwarp();

        // O += P @ V : A from sPw [row][key], B from Vt [hd][key]
        #pragma unroll
        for (int kc = 0; kc < 4; kc++) {
            uint32_t av[4];
            av[0] = *(const uint32_t*)&sPw[g * KP + kc * 16 + 2 * t];
            av[1] = *(const uint32_t*)&sPw[(g + 8) * KP + kc * 16 + 2 * t];
            av[2] = *(const uint32_t*)&sPw[g * KP + kc * 16 + 2 * t + 8];
            av[3] = *(const uint32_t*)&sPw[(g + 8) * KP + kc * 16 + 2 * t + 8];
            #pragma unroll
            for (int nt = 0; nt < 8; nt++) {
                uint32_t b0 = *(const uint32_t*)&Vt[(nt * 8 + g) * KP + kc * 16 + 2 * t];
                uint32_t b1 = *(const uint32_t*)&Vt[(nt * 8 + g) * KP + kc * 16 + 2 * t + 8];
                mma_f16(o[nt], av, b0, b1);
            }
        }
        __syncthreads();
    }

    // normalize, convert to half, stage, coalesced f4 copy to ctx
    const float il0 = 1.0f / l0, il1 = 1.0f / l1;
    #pragma unroll
    for (int nt = 0; nt < 8; nt++) {
        int j0 = nt * 8 + 2 * t;
        *(uint32_t*)&sPw[g * KP + j0]       = h2(o[nt][0] * il0, o[nt][1] * il0);
        *(uint32_t*)&sPw[(g + 8) * KP + j0] = h2(o[nt][2] * il1, o[nt][3] * il1);
    }
    __syncwarp();
    __half* cb = g_ctxh + ((size_t)b * NN + qrow) * DOUTC + h * HD;
    #pragma unroll
    for (int r = 0; r < 4; r++) {
        int f4  = lane + 32 * r;              // 128 f4 = 16 rows x 8
        int row = f4 >> 3;
        int c16 = f4 & 7;
        *(float4*)(cb + (size_t)row * DOUTC + c16 * 8) =
            *(float4*)&sPw[row * KP + c16 * 8];
    }
}

// ---------------------------------------------------------------------------
extern "C" void kernel_launch(void* const* d_in, const int* in_sizes, int n_in,
                              void* d_out, int out_size) {
    const float* x  = (const float*)d_in[0];
    const int*   am = (const int*)  d_in[1];
    const float* Wq = (const float*)d_in[2];
    const float* Wk = (const float*)d_in[3];
    const float* Wv = (const float*)d_in[4];
    const float* Wo = (const float*)d_in[5];
    const float* bo = (const float*)d_in[6];
    float* out = (float*)d_out;

    cudaFuncSetAttribute(h_gemm, cudaFuncAttributeMaxDynamicSharedMemorySize, HG_SMEM);
    cudaFuncSetAttribute(attn_h, cudaFuncAttributeMaxDynamicSharedMemorySize, ATTN_SMEM);

    round_xh<<<512, 256>>>((const float4*)x);
    prep_wh<<<dim3(DIN / 32, DOUTC / 32, 4), dim3(32, 8)>>>(Wq, Wk, Wv, Wo);
    len_k<<<BB, 256>>>(am);

    h_gemm<<<dim3(BB * NN / 128, DOUTC / 128, 3), 256, HG_SMEM>>>(nullptr, nullptr, 0);
    attn_h<<<dim3(NN / 128, BB * HH), 256, ATTN_SMEM>>>(am);
    h_gemm<<<dim3(BB * NN / 128, DOUTC / 128, 1), 256, HG_SMEM>>>(out, bo, 3);
}